// round 1
// baseline (speedup 1.0000x reference)
#include <cuda_runtime.h>

#define IDIM   1024
#define HDIM   1024
#define NHEADS 16
#define DHEAD  64
#define BATCH  2
#define SEQ    2048
#define MTOT   (BATCH * SEQ)   // 4096

// Scratch (allocation-free rule: __device__ globals)
__device__ float g_q[(size_t)MTOT * HDIM];    // 16 MB
__device__ float g_k[(size_t)MTOT * DHEAD];   // 1 MB
__device__ float g_v[(size_t)MTOT * DHEAD];   // 1 MB
__device__ float g_ctx[(size_t)MTOT * HDIM];  // 16 MB

// ---------------------------------------------------------------------------
// Tiled SGEMM with bias: C[M,N] = A[M,K] @ W[K,N] + bias[N]
// BM x BN block tile, BK k-step, TM x TN register microtile per thread.
// All dims assumed divisible by tile sizes (true for this problem).
// ---------------------------------------------------------------------------
template <int BM, int BN, int BK, int TM, int TN>
__global__ void __launch_bounds__((BM / TM) * (BN / TN))
gemm_bias(const float* __restrict__ A, const float* __restrict__ W,
          const float* __restrict__ bias, float* __restrict__ C,
          int M, int N, int K)
{
    constexpr int NT = (BM / TM) * (BN / TN);
    __shared__ float As[BK][BM];   // A tile stored k-major (transposed)
    __shared__ float Bs[BK][BN];

    const int tid = threadIdx.x;
    const int m0 = blockIdx.y * BM;
    const int n0 = blockIdx.x * BN;
    const int tx = tid % (BN / TN);
    const int ty = tid / (BN / TN);

    float acc[TM][TN];
#pragma unroll
    for (int i = 0; i < TM; i++)
#pragma unroll
        for (int j = 0; j < TN; j++) acc[i][j] = 0.f;

    constexpr int A_F4 = BM * BK / 4;
    constexpr int B_F4 = BK * BN / 4;
    static_assert(A_F4 <= NT && B_F4 <= NT, "loader mapping assumes <=1 f4/thread");

    for (int kk = 0; kk < K; kk += BK) {
        if (tid < A_F4) {
            int row = tid / (BK / 4);
            int kq = (tid % (BK / 4)) * 4;
            float4 v = *reinterpret_cast<const float4*>(
                &A[(size_t)(m0 + row) * K + kk + kq]);
            As[kq + 0][row] = v.x;
            As[kq + 1][row] = v.y;
            As[kq + 2][row] = v.z;
            As[kq + 3][row] = v.w;
        }
        if (tid < B_F4) {
            int row = tid / (BN / 4);
            int nq = (tid % (BN / 4)) * 4;
            *reinterpret_cast<float4*>(&Bs[row][nq]) =
                *reinterpret_cast<const float4*>(
                    &W[(size_t)(kk + row) * N + n0 + nq]);
        }
        __syncthreads();

#pragma unroll
        for (int k = 0; k < BK; k++) {
            float ar[TM], br[TN];
#pragma unroll
            for (int i = 0; i < TM; i += 4)
                *reinterpret_cast<float4*>(&ar[i]) =
                    *reinterpret_cast<const float4*>(&As[k][ty * TM + i]);
#pragma unroll
            for (int j = 0; j < TN; j += 4)
                *reinterpret_cast<float4*>(&br[j]) =
                    *reinterpret_cast<const float4*>(&Bs[k][tx * TN + j]);
#pragma unroll
            for (int i = 0; i < TM; i++)
#pragma unroll
                for (int j = 0; j < TN; j++)
                    acc[i][j] = fmaf(ar[i], br[j], acc[i][j]);
        }
        __syncthreads();
    }

#pragma unroll
    for (int i = 0; i < TM; i++) {
        int m = m0 + ty * TM + i;
#pragma unroll
        for (int j = 0; j < TN; j += 4) {
            int n = n0 + tx * TN + j;
            float4 o;
            o.x = acc[i][j + 0] + bias[n + 0];
            o.y = acc[i][j + 1] + bias[n + 1];
            o.z = acc[i][j + 2] + bias[n + 2];
            o.w = acc[i][j + 3] + bias[n + 3];
            *reinterpret_cast<float4*>(&C[(size_t)m * N + n]) = o;
        }
    }
}

// ---------------------------------------------------------------------------
// MQA flash attention: per block = one (batch, head, 64-query tile).
// Streams K/V in 32-row tiles with online softmax. Single shared K/V head.
// scores = (Q_h @ K^T) / sqrt(HDIM); out = softmax(scores) @ V.
// Thread layout: g = tid>>4 picks a 4-query row group (16 groups x 4 = 64 q),
// c = tid&15 picks 2 key cols (scores) / 4 head dims (PV). The 16 lanes
// sharing a row group are consecutive, so row stats reduce via shfl.xor 1..8.
// ---------------------------------------------------------------------------
__global__ void __launch_bounds__(256)
mqa_attn(const float* __restrict__ Qp, const float* __restrict__ Kp,
         const float* __restrict__ Vp, float* __restrict__ ctx)
{
    __shared__ float Qs[64][64];      // 16 KB
    __shared__ float Ks[32][65];      // 8.125 KB (pad 65: conflict-free col reads)
    __shared__ float Vs[32][64];      // 8 KB
    __shared__ float Ps[64][32];      // 8 KB

    const int tid = threadIdx.x;
    const int b = blockIdx.z;
    const int h = blockIdx.y;
    const int q0 = blockIdx.x * 64;
    const int g = tid >> 4;
    const int c = tid & 15;
    const int qr = g * 4;
    const int kc0 = c * 2;
    const int dc0 = c * 4;

    // Load Q tile: rows q0..q0+63, cols h*64..h*64+63
    {
        const float* qb = Qp + (size_t)(b * SEQ + q0) * HDIM + h * DHEAD;
        for (int i = tid; i < 64 * 16; i += 256) {
            int r = i >> 4, f = (i & 15) * 4;
            *reinterpret_cast<float4*>(&Qs[r][f]) =
                *reinterpret_cast<const float4*>(&qb[(size_t)r * HDIM + f]);
        }
    }

    float m[4], l[4], O[4][4];
#pragma unroll
    for (int i = 0; i < 4; i++) {
        m[i] = -1e30f;
        l[i] = 0.f;
#pragma unroll
        for (int j = 0; j < 4; j++) O[i][j] = 0.f;
    }

    const float* kb = Kp + (size_t)b * SEQ * DHEAD;
    const float* vb = Vp + (size_t)b * SEQ * DHEAD;
    const float sc = 0.03125f;  // 1/sqrt(1024)

    for (int kt = 0; kt < SEQ; kt += 32) {
        // Load K (padded-65 rows, scalar stores) and V (float4) tiles
        for (int i = tid; i < 32 * 16; i += 256) {
            int r = i >> 4, f = (i & 15) * 4;
            float4 kv = *reinterpret_cast<const float4*>(
                &kb[(size_t)(kt + r) * DHEAD + f]);
            Ks[r][f + 0] = kv.x;
            Ks[r][f + 1] = kv.y;
            Ks[r][f + 2] = kv.z;
            Ks[r][f + 3] = kv.w;
            *reinterpret_cast<float4*>(&Vs[r][f]) =
                *reinterpret_cast<const float4*>(&vb[(size_t)(kt + r) * DHEAD + f]);
        }
        __syncthreads();

        // Scores: s[i][j] = Q[qr+i] . K[kc0+j]
        float s[4][2];
#pragma unroll
        for (int i = 0; i < 4; i++) { s[i][0] = 0.f; s[i][1] = 0.f; }
#pragma unroll 8
        for (int d = 0; d < 64; d++) {
            float k0 = Ks[kc0 + 0][d];
            float k1 = Ks[kc0 + 1][d];
#pragma unroll
            for (int i = 0; i < 4; i++) {
                float qv = Qs[qr + i][d];
                s[i][0] = fmaf(qv, k0, s[i][0]);
                s[i][1] = fmaf(qv, k1, s[i][1]);
            }
        }

        // Online softmax update (row stats across the 16 lanes of this group)
#pragma unroll
        for (int i = 0; i < 4; i++) {
            s[i][0] *= sc;
            s[i][1] *= sc;
            float rm = fmaxf(s[i][0], s[i][1]);
            rm = fmaxf(rm, __shfl_xor_sync(0xffffffffu, rm, 1));
            rm = fmaxf(rm, __shfl_xor_sync(0xffffffffu, rm, 2));
            rm = fmaxf(rm, __shfl_xor_sync(0xffffffffu, rm, 4));
            rm = fmaxf(rm, __shfl_xor_sync(0xffffffffu, rm, 8));
            float mn = fmaxf(m[i], rm);
            float f = __expf(m[i] - mn);
            float p0 = __expf(s[i][0] - mn);
            float p1 = __expf(s[i][1] - mn);
            float rs = p0 + p1;
            rs += __shfl_xor_sync(0xffffffffu, rs, 1);
            rs += __shfl_xor_sync(0xffffffffu, rs, 2);
            rs += __shfl_xor_sync(0xffffffffu, rs, 4);
            rs += __shfl_xor_sync(0xffffffffu, rs, 8);
            l[i] = l[i] * f + rs;
            m[i] = mn;
#pragma unroll
            for (int j = 0; j < 4; j++) O[i][j] *= f;
            Ps[qr + i][kc0 + 0] = p0;
            Ps[qr + i][kc0 + 1] = p1;
        }
        __syncthreads();

        // O += P @ V  (thread: 4 q rows x 4 head dims)
#pragma unroll 8
        for (int k = 0; k < 32; k++) {
            float4 v4 = *reinterpret_cast<const float4*>(&Vs[k][dc0]);
#pragma unroll
            for (int i = 0; i < 4; i++) {
                float pv = Ps[qr + i][k];
                O[i][0] = fmaf(pv, v4.x, O[i][0]);
                O[i][1] = fmaf(pv, v4.y, O[i][1]);
                O[i][2] = fmaf(pv, v4.z, O[i][2]);
                O[i][3] = fmaf(pv, v4.w, O[i][3]);
            }
        }
        __syncthreads();  // protect Vs/Ps before next tile load
    }

#pragma unroll
    for (int i = 0; i < 4; i++) {
        float inv = 1.f / l[i];
        float4 o = make_float4(O[i][0] * inv, O[i][1] * inv,
                               O[i][2] * inv, O[i][3] * inv);
        *reinterpret_cast<float4*>(
            &ctx[(size_t)(b * SEQ + q0 + qr + i) * HDIM + h * DHEAD + dc0]) = o;
    }
}

// ---------------------------------------------------------------------------
extern "C" void kernel_launch(void* const* d_in, const int* in_sizes, int n_in,
                              void* d_out, int out_size)
{
    const float* query = (const float*)d_in[0];
    const float* key   = (const float*)d_in[1];
    const float* value = (const float*)d_in[2];
    const float* Wq    = (const float*)d_in[3];
    const float* bq    = (const float*)d_in[4];
    const float* Wk    = (const float*)d_in[5];
    const float* bk    = (const float*)d_in[6];
    const float* Wv    = (const float*)d_in[7];
    const float* bv    = (const float*)d_in[8];
    const float* Wo    = (const float*)d_in[9];
    const float* bo    = (const float*)d_in[10];
    float* out = (float*)d_out;

    float *q, *k, *v, *ctx;
    cudaGetSymbolAddress((void**)&q, g_q);
    cudaGetSymbolAddress((void**)&k, g_k);
    cudaGetSymbolAddress((void**)&v, g_v);
    cudaGetSymbolAddress((void**)&ctx, g_ctx);

    // Projections
    gemm_bias<128, 128, 8, 8, 8>
        <<<dim3(HDIM / 128, MTOT / 128), 256>>>(query, Wq, bq, q, MTOT, HDIM, IDIM);
    gemm_bias<128, 64, 8, 8, 4>
        <<<dim3(1, MTOT / 128), 256>>>(key, Wk, bk, k, MTOT, DHEAD, IDIM);
    gemm_bias<128, 64, 8, 8, 4>
        <<<dim3(1, MTOT / 128), 256>>>(value, Wv, bv, v, MTOT, DHEAD, IDIM);

    // Attention
    mqa_attn<<<dim3(SEQ / 64, NHEADS, BATCH), 256>>>(q, k, v, ctx);

    // Output projection -> d_out
    gemm_bias<128, 128, 8, 8, 8>
        <<<dim3(IDIM / 128, MTOT / 128), 256>>>(ctx, Wo, bo, out, MTOT, IDIM, HDIM);
}

// round 4
// speedup vs baseline: 2.0822x; 2.0822x over previous
#include <cuda_runtime.h>
#include <cstdint>

#define IDIM   1024
#define HDIM   1024
#define NHEADS 16
#define DHEAD  64
#define BATCH  2
#define SEQ    2048
#define MTOT   (BATCH * SEQ)   // 4096

// Scratch (allocation-free rule: __device__ globals)
__device__ float g_q[(size_t)MTOT * HDIM];    // 16 MB
__device__ float g_k[(size_t)MTOT * DHEAD];   // 1 MB
__device__ float g_v[(size_t)MTOT * DHEAD];   // 1 MB
__device__ float g_ctx[(size_t)MTOT * HDIM];  // 16 MB

__device__ __forceinline__ uint32_t f2tf32(float f) {
    uint32_t u;
    asm("cvt.rna.tf32.f32 %0, %1;" : "=r"(u) : "f"(f));
    return u;
}

// D = A(16x8) * B(8x8) + D, tf32 in / fp32 accum. row.col.
// A frag: a0=(g, t), a1=(g+8, t), a2=(g, t+4), a3=(g+8, t+4)   [g=lane/4, t=lane%4]
// B frag: b0=(k=t, n=g), b1=(k=t+4, n=g)
// C frag: c0=(g, 2t), c1=(g, 2t+1), c2=(g+8, 2t), c3=(g+8, 2t+1)
__device__ __forceinline__ void mma_tf32(float (&d)[4], const uint32_t (&a)[4],
                                         const uint32_t (&b)[2]) {
    asm volatile(
        "mma.sync.aligned.m16n8k8.row.col.f32.tf32.tf32.f32 "
        "{%0,%1,%2,%3}, {%4,%5,%6,%7}, {%8,%9}, {%0,%1,%2,%3};"
        : "+f"(d[0]), "+f"(d[1]), "+f"(d[2]), "+f"(d[3])
        : "r"(a[0]), "r"(a[1]), "r"(a[2]), "r"(a[3]), "r"(b[0]), "r"(b[1]));
}

// ---------------------------------------------------------------------------
// tf32 tensor-core GEMM: C[M,N] = A[M,K] @ W[K,N] + bias[N]
// 256 threads = 8 warps (2x4), BMxBNx16 tile, double-buffered smem.
// As[m][k] (pad 19), Ws[n][k] transposed (pad 19).
// ---------------------------------------------------------------------------
template <int BM, int BN>
__global__ void __launch_bounds__(256)
gemm_tf32(const float* __restrict__ A, const float* __restrict__ W,
          const float* __restrict__ bias, float* __restrict__ C,
          int M, int N, int K)
{
    constexpr int BK  = 16;
    constexpr int PAD = 19;          // 19 mod 32 = 3 -> frag LDS <=2-way
    constexpr int MT  = (BM / 2) / 16;
    constexpr int NT  = (BN / 4) / 8;
    constexpr int APF = BM / 64;     // float4 per thread for A tile
    constexpr int WPF = BN / 64;     // float4 per thread for W tile

    __shared__ uint32_t As[2][BM][PAD];
    __shared__ uint32_t Ws[2][BN][PAD];

    const int tid  = threadIdx.x;
    const int lane = tid & 31;
    const int warp = tid >> 5;
    const int wm   = warp >> 2;       // 0..1
    const int wn   = warp & 3;        // 0..3
    const int m0   = blockIdx.y * BM;
    const int n0   = blockIdx.x * BN;

    float acc[MT][NT][4];
#pragma unroll
    for (int i = 0; i < MT; i++)
#pragma unroll
        for (int j = 0; j < NT; j++)
#pragma unroll
            for (int e = 0; e < 4; e++) acc[i][j][e] = 0.f;

    // ---- load tile 0 ----
#pragma unroll
    for (int i = 0; i < APF; i++) {
        int idx = tid + i * 256;
        int row = idx >> 2, kq = (idx & 3) * 4;
        float4 v = *reinterpret_cast<const float4*>(&A[(size_t)(m0 + row) * K + kq]);
        As[0][row][kq + 0] = f2tf32(v.x);
        As[0][row][kq + 1] = f2tf32(v.y);
        As[0][row][kq + 2] = f2tf32(v.z);
        As[0][row][kq + 3] = f2tf32(v.w);
    }
#pragma unroll
    for (int i = 0; i < WPF; i++) {
        int idx = tid + i * 256;
        int n4 = idx % (BN / 4), kr = idx / (BN / 4);
        float4 v = *reinterpret_cast<const float4*>(&W[(size_t)kr * N + n0 + n4 * 4]);
        Ws[0][n4 * 4 + 0][kr] = f2tf32(v.x);
        Ws[0][n4 * 4 + 1][kr] = f2tf32(v.y);
        Ws[0][n4 * 4 + 2][kr] = f2tf32(v.z);
        Ws[0][n4 * 4 + 3][kr] = f2tf32(v.w);
    }
    __syncthreads();

    const int NITER = K / BK;
    for (int t = 0; t < NITER; t++) {
        const int s = t & 1;

        // prefetch next tile into registers
        float4 pfa[APF], pfw[WPF];
        if (t + 1 < NITER) {
            const int kk = (t + 1) * BK;
#pragma unroll
            for (int i = 0; i < APF; i++) {
                int idx = tid + i * 256;
                int row = idx >> 2, kq = (idx & 3) * 4;
                pfa[i] = *reinterpret_cast<const float4*>(
                    &A[(size_t)(m0 + row) * K + kk + kq]);
            }
#pragma unroll
            for (int i = 0; i < WPF; i++) {
                int idx = tid + i * 256;
                int n4 = idx % (BN / 4), kr = idx / (BN / 4);
                pfw[i] = *reinterpret_cast<const float4*>(
                    &W[(size_t)(kk + kr) * N + n0 + n4 * 4]);
            }
        }

        // compute on stage s
#pragma unroll
        for (int ks = 0; ks < 2; ks++) {
            const int c = ks * 8 + (lane & 3);
            uint32_t af[MT][4];
#pragma unroll
            for (int mi = 0; mi < MT; mi++) {
                int r = wm * (BM / 2) + mi * 16 + (lane >> 2);
                af[mi][0] = As[s][r][c];
                af[mi][1] = As[s][r + 8][c];
                af[mi][2] = As[s][r][c + 4];
                af[mi][3] = As[s][r + 8][c + 4];
            }
#pragma unroll
            for (int ni = 0; ni < NT; ni++) {
                int nr = wn * (BN / 4) + ni * 8 + (lane >> 2);
                uint32_t bf[2] = { Ws[s][nr][c], Ws[s][nr][c + 4] };
#pragma unroll
                for (int mi = 0; mi < MT; mi++)
                    mma_tf32(acc[mi][ni], af[mi], bf);
            }
        }

        // commit prefetch to stage s^1
        if (t + 1 < NITER) {
            const int d = s ^ 1;
#pragma unroll
            for (int i = 0; i < APF; i++) {
                int idx = tid + i * 256;
                int row = idx >> 2, kq = (idx & 3) * 4;
                As[d][row][kq + 0] = f2tf32(pfa[i].x);
                As[d][row][kq + 1] = f2tf32(pfa[i].y);
                As[d][row][kq + 2] = f2tf32(pfa[i].z);
                As[d][row][kq + 3] = f2tf32(pfa[i].w);
            }
#pragma unroll
            for (int i = 0; i < WPF; i++) {
                int idx = tid + i * 256;
                int n4 = idx % (BN / 4), kr = idx / (BN / 4);
                Ws[d][n4 * 4 + 0][kr] = f2tf32(pfw[i].x);
                Ws[d][n4 * 4 + 1][kr] = f2tf32(pfw[i].y);
                Ws[d][n4 * 4 + 2][kr] = f2tf32(pfw[i].z);
                Ws[d][n4 * 4 + 3][kr] = f2tf32(pfw[i].w);
            }
        }
        __syncthreads();
    }

    // epilogue: bias + store (float2)
#pragma unroll
    for (int mi = 0; mi < MT; mi++) {
        int row = m0 + wm * (BM / 2) + mi * 16 + (lane >> 2);
#pragma unroll
        for (int ni = 0; ni < NT; ni++) {
            int col = n0 + wn * (BN / 4) + ni * 8 + 2 * (lane & 3);
            float b0 = bias[col], b1 = bias[col + 1];
            float2 v0 = make_float2(acc[mi][ni][0] + b0, acc[mi][ni][1] + b1);
            float2 v1 = make_float2(acc[mi][ni][2] + b0, acc[mi][ni][3] + b1);
            *reinterpret_cast<float2*>(&C[(size_t)row * N + col]) = v0;
            *reinterpret_cast<float2*>(&C[(size_t)(row + 8) * N + col]) = v1;
        }
    }
}

// ---------------------------------------------------------------------------
// Tensor-core MQA flash attention. Block = (b, h, 64-q-tile), 128 threads.
// Per warp: 16 q rows. K streamed in 32-key tiles.
//   S = (Q*2^-5) @ K^T  via mma (Ks[key][dim] is exactly col-major B)
//   online softmax on C frags (quad shfl), P -> warp-private smem -> A frags
//   O += P @ V with Vt[dim][key] (transposed in smem)
// ---------------------------------------------------------------------------
__global__ void __launch_bounds__(128)
mqa_attn_tc(const float* __restrict__ Qp, const float* __restrict__ Kp,
            const float* __restrict__ Vp, float* __restrict__ ctx)
{
    __shared__ uint32_t Qs[64][67];   // 16.75 KB (67 mod 32 = 3)
    __shared__ uint32_t Ks[32][67];   //  8.4 KB
    __shared__ uint32_t Vt[64][35];   //  8.75 KB (35 mod 32 = 3)
    __shared__ uint32_t Ps[64][35];   //  8.75 KB

    const int tid  = threadIdx.x;
    const int lane = tid & 31;
    const int warp = tid >> 5;
    const int b    = blockIdx.z;
    const int h    = blockIdx.y;
    const int q0   = blockIdx.x * 64;
    const int g    = lane >> 2;       // 0..7
    const int tq   = lane & 3;        // 0..3

    // Load + pre-scale Q tile (scale 2^-5 exact in tf32)
    {
        const float* qb = Qp + (size_t)(b * SEQ + q0) * HDIM + h * DHEAD;
        for (int idx = tid; idx < 1024; idx += 128) {
            int r = idx >> 4, f4 = (idx & 15) * 4;
            float4 v = *reinterpret_cast<const float4*>(&qb[(size_t)r * HDIM + f4]);
            Qs[r][f4 + 0] = f2tf32(v.x * 0.03125f);
            Qs[r][f4 + 1] = f2tf32(v.y * 0.03125f);
            Qs[r][f4 + 2] = f2tf32(v.z * 0.03125f);
            Qs[r][f4 + 3] = f2tf32(v.w * 0.03125f);
        }
    }

    float m2[2] = { -1e30f, -1e30f };
    float l2[2] = { 0.f, 0.f };
    float o[8][4];
#pragma unroll
    for (int i = 0; i < 8; i++)
#pragma unroll
        for (int j = 0; j < 4; j++) o[i][j] = 0.f;

    const float* kb = Kp + (size_t)b * SEQ * DHEAD;
    const float* vb = Vp + (size_t)b * SEQ * DHEAD;

    for (int kt = 0; kt < SEQ; kt += 32) {
        // load K tile [32 keys][64 dim] and V tile transposed [64 dim][32 keys]
        for (int idx = tid; idx < 512; idx += 128) {
            int r = idx >> 4, f4 = (idx & 15) * 4;
            float4 kv = *reinterpret_cast<const float4*>(&kb[(size_t)(kt + r) * DHEAD + f4]);
            Ks[r][f4 + 0] = f2tf32(kv.x);
            Ks[r][f4 + 1] = f2tf32(kv.y);
            Ks[r][f4 + 2] = f2tf32(kv.z);
            Ks[r][f4 + 3] = f2tf32(kv.w);
            float4 vv = *reinterpret_cast<const float4*>(&vb[(size_t)(kt + r) * DHEAD + f4]);
            Vt[f4 + 0][r] = f2tf32(vv.x);
            Vt[f4 + 1][r] = f2tf32(vv.y);
            Vt[f4 + 2][r] = f2tf32(vv.z);
            Vt[f4 + 3][r] = f2tf32(vv.w);
        }
        __syncthreads();

        // S = Q @ K^T : 4 n-tiles (32 keys), k over 64 dims
        float s4[4][4];
#pragma unroll
        for (int nt = 0; nt < 4; nt++)
#pragma unroll
            for (int e = 0; e < 4; e++) s4[nt][e] = 0.f;

#pragma unroll
        for (int ks = 0; ks < 8; ks++) {
            const int c = ks * 8 + tq;
            const int r = warp * 16 + g;
            uint32_t af[4] = { Qs[r][c], Qs[r + 8][c], Qs[r][c + 4], Qs[r + 8][c + 4] };
#pragma unroll
            for (int nt = 0; nt < 4; nt++) {
                int n = nt * 8 + g;
                uint32_t bf[2] = { Ks[n][c], Ks[n][c + 4] };
                mma_tf32(s4[nt], af, bf);
            }
        }

        // online softmax per row-half
#pragma unroll
        for (int half = 0; half < 2; half++) {
            float vmax = -1e30f;
#pragma unroll
            for (int nt = 0; nt < 4; nt++) {
                vmax = fmaxf(vmax, s4[nt][2 * half + 0]);
                vmax = fmaxf(vmax, s4[nt][2 * half + 1]);
            }
            vmax = fmaxf(vmax, __shfl_xor_sync(0xffffffffu, vmax, 1));
            vmax = fmaxf(vmax, __shfl_xor_sync(0xffffffffu, vmax, 2));
            float mn = fmaxf(m2[half], vmax);
            float f  = __expf(m2[half] - mn);
            m2[half] = mn;
            float sum = 0.f;
            const int prow = warp * 16 + g + 8 * half;
#pragma unroll
            for (int nt = 0; nt < 4; nt++) {
                float p0 = __expf(s4[nt][2 * half + 0] - mn);
                float p1 = __expf(s4[nt][2 * half + 1] - mn);
                sum += p0 + p1;
                Ps[prow][nt * 8 + 2 * tq + 0] = f2tf32(p0);
                Ps[prow][nt * 8 + 2 * tq + 1] = f2tf32(p1);
            }
            sum += __shfl_xor_sync(0xffffffffu, sum, 1);
            sum += __shfl_xor_sync(0xffffffffu, sum, 2);
            l2[half] = l2[half] * f + sum;
#pragma unroll
            for (int nt = 0; nt < 8; nt++) {
                o[nt][2 * half + 0] *= f;
                o[nt][2 * half + 1] *= f;
            }
        }
        __syncwarp();

        // O += P @ V : 8 n-tiles (64 dims), k over 32 keys
#pragma unroll
        for (int ks = 0; ks < 4; ks++) {
            const int c = ks * 8 + tq;
            const int r = warp * 16 + g;
            uint32_t af[4] = { Ps[r][c], Ps[r + 8][c], Ps[r][c + 4], Ps[r + 8][c + 4] };
#pragma unroll
            for (int nt = 0; nt < 8; nt++) {
                int n = nt * 8 + g;
                uint32_t bf[2] = { Vt[n][c], Vt[n][c + 4] };
                mma_tf32(o[nt], af, bf);
            }
        }
        __syncthreads();   // all warps done with Ks/Vt before next tile load
    }

    // finalize: divide by l, write ctx
    const float inv0 = 1.f / l2[0];
    const float inv1 = 1.f / l2[1];
    const int grow = b * SEQ + q0 + warp * 16 + g;
#pragma unroll
    for (int nt = 0; nt < 8; nt++) {
        int col = h * DHEAD + nt * 8 + 2 * tq;
        float2 v0 = make_float2(o[nt][0] * inv0, o[nt][1] * inv0);
        float2 v1 = make_float2(o[nt][2] * inv1, o[nt][3] * inv1);
        *reinterpret_cast<float2*>(&ctx[(size_t)grow * HDIM + col]) = v0;
        *reinterpret_cast<float2*>(&ctx[(size_t)(grow + 8) * HDIM + col]) = v1;
    }
}

// ---------------------------------------------------------------------------
extern "C" void kernel_launch(void* const* d_in, const int* in_sizes, int n_in,
                              void* d_out, int out_size)
{
    const float* query = (const float*)d_in[0];
    const float* key   = (const float*)d_in[1];
    const float* value = (const float*)d_in[2];
    const float* Wq    = (const float*)d_in[3];
    const float* bq    = (const float*)d_in[4];
    const float* Wk    = (const float*)d_in[5];
    const float* bk    = (const float*)d_in[6];
    const float* Wv    = (const float*)d_in[7];
    const float* bv    = (const float*)d_in[8];
    const float* Wo    = (const float*)d_in[9];
    const float* bo    = (const float*)d_in[10];
    float* out = (float*)d_out;

    float *q, *k, *v, *ctx;
    cudaGetSymbolAddress((void**)&q, g_q);
    cudaGetSymbolAddress((void**)&k, g_k);
    cudaGetSymbolAddress((void**)&v, g_v);
    cudaGetSymbolAddress((void**)&ctx, g_ctx);

    // Projections (tf32 tensor cores)
    gemm_tf32<128, 128><<<dim3(HDIM / 128, MTOT / 128), 256>>>(
        query, Wq, bq, q, MTOT, HDIM, IDIM);
    gemm_tf32<128, 64><<<dim3(1, MTOT / 128), 256>>>(
        key, Wk, bk, k, MTOT, DHEAD, IDIM);
    gemm_tf32<128, 64><<<dim3(1, MTOT / 128), 256>>>(
        value, Wv, bv, v, MTOT, DHEAD, IDIM);

    // Attention (tensor cores)
    mqa_attn_tc<<<dim3(SEQ / 64, NHEADS, BATCH), 128>>>(q, k, v, ctx);

    // Output projection -> d_out
    gemm_tf32<128, 128><<<dim3(IDIM / 128, MTOT / 128), 256>>>(
        ctx, Wo, bo, out, MTOT, IDIM, HDIM);
}

// round 5
// speedup vs baseline: 2.0870x; 1.0023x over previous
#include <cuda_runtime.h>
#include <cstdint>

#define IDIM   1024
#define HDIM   1024
#define NHEADS 16
#define DHEAD  64
#define BATCH  2
#define SEQ    2048
#define MTOT   (BATCH * SEQ)   // 4096

// Scratch (allocation-free rule: __device__ globals)
__device__ float g_q[(size_t)MTOT * HDIM];    // 16 MB
__device__ float g_k[(size_t)MTOT * DHEAD];   // 1 MB
__device__ float g_v[(size_t)MTOT * DHEAD];   // 1 MB
__device__ float g_ctx[(size_t)MTOT * HDIM];  // 16 MB

__device__ __forceinline__ uint32_t f2tf32(float f) {
    uint32_t u;
    asm("cvt.rna.tf32.f32 %0, %1;" : "=r"(u) : "f"(f));
    return u;
}

// D = A(16x8) * B(8x8) + D, tf32 in / fp32 accum. row.col.
// A frag: a0=(g, t), a1=(g+8, t), a2=(g, t+4), a3=(g+8, t+4)   [g=lane/4, t=lane%4]
// B frag: b0=(k=t, n=g), b1=(k=t+4, n=g)
// C frag: c0=(g, 2t), c1=(g, 2t+1), c2=(g+8, 2t), c3=(g+8, 2t+1)
__device__ __forceinline__ void mma_tf32(float (&d)[4], const uint32_t (&a)[4],
                                         const uint32_t (&b)[2]) {
    asm volatile(
        "mma.sync.aligned.m16n8k8.row.col.f32.tf32.tf32.f32 "
        "{%0,%1,%2,%3}, {%4,%5,%6,%7}, {%8,%9}, {%0,%1,%2,%3};"
        : "+f"(d[0]), "+f"(d[1]), "+f"(d[2]), "+f"(d[3])
        : "r"(a[0]), "r"(a[1]), "r"(a[2]), "r"(a[3]), "r"(b[0]), "r"(b[1]));
}

// ---------------------------------------------------------------------------
// tf32 tensor-core GEMM: C[M,N] = A[M,K] @ W[K,N] + bias[N]
// 256 threads = 8 warps (2x4), BMxBNx16 tile, double-buffered smem.
// As[m][k] (pad 19), Ws[n][k] transposed (pad 19).
// ---------------------------------------------------------------------------
template <int BM, int BN>
__global__ void __launch_bounds__(256)
gemm_tf32(const float* __restrict__ A, const float* __restrict__ W,
          const float* __restrict__ bias, float* __restrict__ C,
          int M, int N, int K)
{
    constexpr int BK  = 16;
    constexpr int PAD = 19;          // 19 mod 32 = 3 -> frag LDS <=2-way
    constexpr int MT  = (BM / 2) / 16;
    constexpr int NT  = (BN / 4) / 8;
    constexpr int APF = BM / 64;     // float4 per thread for A tile
    constexpr int WPF = BN / 64;     // float4 per thread for W tile

    __shared__ uint32_t As[2][BM][PAD];
    __shared__ uint32_t Ws[2][BN][PAD];

    const int tid  = threadIdx.x;
    const int lane = tid & 31;
    const int warp = tid >> 5;
    const int wm   = warp >> 2;       // 0..1
    const int wn   = warp & 3;        // 0..3
    const int m0   = blockIdx.y * BM;
    const int n0   = blockIdx.x * BN;

    float acc[MT][NT][4];
#pragma unroll
    for (int i = 0; i < MT; i++)
#pragma unroll
        for (int j = 0; j < NT; j++)
#pragma unroll
            for (int e = 0; e < 4; e++) acc[i][j][e] = 0.f;

    // ---- load tile 0 ----
#pragma unroll
    for (int i = 0; i < APF; i++) {
        int idx = tid + i * 256;
        int row = idx >> 2, kq = (idx & 3) * 4;
        float4 v = *reinterpret_cast<const float4*>(&A[(size_t)(m0 + row) * K + kq]);
        As[0][row][kq + 0] = f2tf32(v.x);
        As[0][row][kq + 1] = f2tf32(v.y);
        As[0][row][kq + 2] = f2tf32(v.z);
        As[0][row][kq + 3] = f2tf32(v.w);
    }
#pragma unroll
    for (int i = 0; i < WPF; i++) {
        int idx = tid + i * 256;
        int n4 = idx % (BN / 4), kr = idx / (BN / 4);
        float4 v = *reinterpret_cast<const float4*>(&W[(size_t)kr * N + n0 + n4 * 4]);
        Ws[0][n4 * 4 + 0][kr] = f2tf32(v.x);
        Ws[0][n4 * 4 + 1][kr] = f2tf32(v.y);
        Ws[0][n4 * 4 + 2][kr] = f2tf32(v.z);
        Ws[0][n4 * 4 + 3][kr] = f2tf32(v.w);
    }
    __syncthreads();

    const int NITER = K / BK;
    for (int t = 0; t < NITER; t++) {
        const int s = t & 1;

        // prefetch next tile into registers
        float4 pfa[APF], pfw[WPF];
        if (t + 1 < NITER) {
            const int kk = (t + 1) * BK;
#pragma unroll
            for (int i = 0; i < APF; i++) {
                int idx = tid + i * 256;
                int row = idx >> 2, kq = (idx & 3) * 4;
                pfa[i] = *reinterpret_cast<const float4*>(
                    &A[(size_t)(m0 + row) * K + kk + kq]);
            }
#pragma unroll
            for (int i = 0; i < WPF; i++) {
                int idx = tid + i * 256;
                int n4 = idx % (BN / 4), kr = idx / (BN / 4);
                pfw[i] = *reinterpret_cast<const float4*>(
                    &W[(size_t)(kk + kr) * N + n0 + n4 * 4]);
            }
        }

        // compute on stage s
#pragma unroll
        for (int ks = 0; ks < 2; ks++) {
            const int c = ks * 8 + (lane & 3);
            uint32_t af[MT][4];
#pragma unroll
            for (int mi = 0; mi < MT; mi++) {
                int r = wm * (BM / 2) + mi * 16 + (lane >> 2);
                af[mi][0] = As[s][r][c];
                af[mi][1] = As[s][r + 8][c];
                af[mi][2] = As[s][r][c + 4];
                af[mi][3] = As[s][r + 8][c + 4];
            }
#pragma unroll
            for (int ni = 0; ni < NT; ni++) {
                int nr = wn * (BN / 4) + ni * 8 + (lane >> 2);
                uint32_t bf[2] = { Ws[s][nr][c], Ws[s][nr][c + 4] };
#pragma unroll
                for (int mi = 0; mi < MT; mi++)
                    mma_tf32(acc[mi][ni], af[mi], bf);
            }
        }

        // commit prefetch to stage s^1
        if (t + 1 < NITER) {
            const int d = s ^ 1;
#pragma unroll
            for (int i = 0; i < APF; i++) {
                int idx = tid + i * 256;
                int row = idx >> 2, kq = (idx & 3) * 4;
                As[d][row][kq + 0] = f2tf32(pfa[i].x);
                As[d][row][kq + 1] = f2tf32(pfa[i].y);
                As[d][row][kq + 2] = f2tf32(pfa[i].z);
                As[d][row][kq + 3] = f2tf32(pfa[i].w);
            }
#pragma unroll
            for (int i = 0; i < WPF; i++) {
                int idx = tid + i * 256;
                int n4 = idx % (BN / 4), kr = idx / (BN / 4);
                Ws[d][n4 * 4 + 0][kr] = f2tf32(pfw[i].x);
                Ws[d][n4 * 4 + 1][kr] = f2tf32(pfw[i].y);
                Ws[d][n4 * 4 + 2][kr] = f2tf32(pfw[i].z);
                Ws[d][n4 * 4 + 3][kr] = f2tf32(pfw[i].w);
            }
        }
        __syncthreads();
    }

    // epilogue: bias + store (float2)
#pragma unroll
    for (int mi = 0; mi < MT; mi++) {
        int row = m0 + wm * (BM / 2) + mi * 16 + (lane >> 2);
#pragma unroll
        for (int ni = 0; ni < NT; ni++) {
            int col = n0 + wn * (BN / 4) + ni * 8 + 2 * (lane & 3);
            float b0 = bias[col], b1 = bias[col + 1];
            float2 v0 = make_float2(acc[mi][ni][0] + b0, acc[mi][ni][1] + b1);
            float2 v1 = make_float2(acc[mi][ni][2] + b0, acc[mi][ni][3] + b1);
            *reinterpret_cast<float2*>(&C[(size_t)row * N + col]) = v0;
            *reinterpret_cast<float2*>(&C[(size_t)(row + 8) * N + col]) = v1;
        }
    }
}

// ---------------------------------------------------------------------------
// Tensor-core MQA flash attention. Block = (b, h, 64-q-tile), 128 threads.
// Per warp: 16 q rows. K streamed in 32-key tiles.
//   S = (Q*2^-5) @ K^T  via mma (Ks[key][dim] is exactly col-major B)
//   online softmax on C frags (quad shfl), P -> warp-private smem -> A frags
//   O += P @ V with Vt[dim][key] (transposed in smem)
// ---------------------------------------------------------------------------
__global__ void __launch_bounds__(128)
mqa_attn_tc(const float* __restrict__ Qp, const float* __restrict__ Kp,
            const float* __restrict__ Vp, float* __restrict__ ctx)
{
    __shared__ uint32_t Qs[64][67];   // 16.75 KB (67 mod 32 = 3)
    __shared__ uint32_t Ks[32][67];   //  8.4 KB
    __shared__ uint32_t Vt[64][35];   //  8.75 KB (35 mod 32 = 3)
    __shared__ uint32_t Ps[64][35];   //  8.75 KB

    const int tid  = threadIdx.x;
    const int lane = tid & 31;
    const int warp = tid >> 5;
    const int b    = blockIdx.z;
    const int h    = blockIdx.y;
    const int q0   = blockIdx.x * 64;
    const int g    = lane >> 2;       // 0..7
    const int tq   = lane & 3;        // 0..3

    // Load + pre-scale Q tile (scale 2^-5 exact in tf32)
    {
        const float* qb = Qp + (size_t)(b * SEQ + q0) * HDIM + h * DHEAD;
        for (int idx = tid; idx < 1024; idx += 128) {
            int r = idx >> 4, f4 = (idx & 15) * 4;
            float4 v = *reinterpret_cast<const float4*>(&qb[(size_t)r * HDIM + f4]);
            Qs[r][f4 + 0] = f2tf32(v.x * 0.03125f);
            Qs[r][f4 + 1] = f2tf32(v.y * 0.03125f);
            Qs[r][f4 + 2] = f2tf32(v.z * 0.03125f);
            Qs[r][f4 + 3] = f2tf32(v.w * 0.03125f);
        }
    }

    float m2[2] = { -1e30f, -1e30f };
    float l2[2] = { 0.f, 0.f };
    float o[8][4];
#pragma unroll
    for (int i = 0; i < 8; i++)
#pragma unroll
        for (int j = 0; j < 4; j++) o[i][j] = 0.f;

    const float* kb = Kp + (size_t)b * SEQ * DHEAD;
    const float* vb = Vp + (size_t)b * SEQ * DHEAD;

    for (int kt = 0; kt < SEQ; kt += 32) {
        // load K tile [32 keys][64 dim] and V tile transposed [64 dim][32 keys]
        for (int idx = tid; idx < 512; idx += 128) {
            int r = idx >> 4, f4 = (idx & 15) * 4;
            float4 kv = *reinterpret_cast<const float4*>(&kb[(size_t)(kt + r) * DHEAD + f4]);
            Ks[r][f4 + 0] = f2tf32(kv.x);
            Ks[r][f4 + 1] = f2tf32(kv.y);
            Ks[r][f4 + 2] = f2tf32(kv.z);
            Ks[r][f4 + 3] = f2tf32(kv.w);
            float4 vv = *reinterpret_cast<const float4*>(&vb[(size_t)(kt + r) * DHEAD + f4]);
            Vt[f4 + 0][r] = f2tf32(vv.x);
            Vt[f4 + 1][r] = f2tf32(vv.y);
            Vt[f4 + 2][r] = f2tf32(vv.z);
            Vt[f4 + 3][r] = f2tf32(vv.w);
        }
        __syncthreads();

        // S = Q @ K^T : 4 n-tiles (32 keys), k over 64 dims
        float s4[4][4];
#pragma unroll
        for (int nt = 0; nt < 4; nt++)
#pragma unroll
            for (int e = 0; e < 4; e++) s4[nt][e] = 0.f;

#pragma unroll
        for (int ks = 0; ks < 8; ks++) {
            const int c = ks * 8 + tq;
            const int r = warp * 16 + g;
            uint32_t af[4] = { Qs[r][c], Qs[r + 8][c], Qs[r][c + 4], Qs[r + 8][c + 4] };
#pragma unroll
            for (int nt = 0; nt < 4; nt++) {
                int n = nt * 8 + g;
                uint32_t bf[2] = { Ks[n][c], Ks[n][c + 4] };
                mma_tf32(s4[nt], af, bf);
            }
        }

        // online softmax per row-half
#pragma unroll
        for (int half = 0; half < 2; half++) {
            float vmax = -1e30f;
#pragma unroll
            for (int nt = 0; nt < 4; nt++) {
                vmax = fmaxf(vmax, s4[nt][2 * half + 0]);
                vmax = fmaxf(vmax, s4[nt][2 * half + 1]);
            }
            vmax = fmaxf(vmax, __shfl_xor_sync(0xffffffffu, vmax, 1));
            vmax = fmaxf(vmax, __shfl_xor_sync(0xffffffffu, vmax, 2));
            float mn = fmaxf(m2[half], vmax);
            float f  = __expf(m2[half] - mn);
            m2[half] = mn;
            float sum = 0.f;
            const int prow = warp * 16 + g + 8 * half;
#pragma unroll
            for (int nt = 0; nt < 4; nt++) {
                float p0 = __expf(s4[nt][2 * half + 0] - mn);
                float p1 = __expf(s4[nt][2 * half + 1] - mn);
                sum += p0 + p1;
                Ps[prow][nt * 8 + 2 * tq + 0] = f2tf32(p0);
                Ps[prow][nt * 8 + 2 * tq + 1] = f2tf32(p1);
            }
            sum += __shfl_xor_sync(0xffffffffu, sum, 1);
            sum += __shfl_xor_sync(0xffffffffu, sum, 2);
            l2[half] = l2[half] * f + sum;
#pragma unroll
            for (int nt = 0; nt < 8; nt++) {
                o[nt][2 * half + 0] *= f;
                o[nt][2 * half + 1] *= f;
            }
        }
        __syncwarp();

        // O += P @ V : 8 n-tiles (64 dims), k over 32 keys
#pragma unroll
        for (int ks = 0; ks < 4; ks++) {
            const int c = ks * 8 + tq;
            const int r = warp * 16 + g;
            uint32_t af[4] = { Ps[r][c], Ps[r + 8][c], Ps[r][c + 4], Ps[r + 8][c + 4] };
#pragma unroll
            for (int nt = 0; nt < 8; nt++) {
                int n = nt * 8 + g;
                uint32_t bf[2] = { Vt[n][c], Vt[n][c + 4] };
                mma_tf32(o[nt], af, bf);
            }
        }
        __syncthreads();   // all warps done with Ks/Vt before next tile load
    }

    // finalize: divide by l, write ctx
    const float inv0 = 1.f / l2[0];
    const float inv1 = 1.f / l2[1];
    const int grow = b * SEQ + q0 + warp * 16 + g;
#pragma unroll
    for (int nt = 0; nt < 8; nt++) {
        int col = h * DHEAD + nt * 8 + 2 * tq;
        float2 v0 = make_float2(o[nt][0] * inv0, o[nt][1] * inv0);
        float2 v1 = make_float2(o[nt][2] * inv1, o[nt][3] * inv1);
        *reinterpret_cast<float2*>(&ctx[(size_t)grow * HDIM + col]) = v0;
        *reinterpret_cast<float2*>(&ctx[(size_t)(grow + 8) * HDIM + col]) = v1;
    }
}

// ---------------------------------------------------------------------------
extern "C" void kernel_launch(void* const* d_in, const int* in_sizes, int n_in,
                              void* d_out, int out_size)
{
    const float* query = (const float*)d_in[0];
    const float* key   = (const float*)d_in[1];
    const float* value = (const float*)d_in[2];
    const float* Wq    = (const float*)d_in[3];
    const float* bq    = (const float*)d_in[4];
    const float* Wk    = (const float*)d_in[5];
    const float* bk    = (const float*)d_in[6];
    const float* Wv    = (const float*)d_in[7];
    const float* bv    = (const float*)d_in[8];
    const float* Wo    = (const float*)d_in[9];
    const float* bo    = (const float*)d_in[10];
    float* out = (float*)d_out;

    float *q, *k, *v, *ctx;
    cudaGetSymbolAddress((void**)&q, g_q);
    cudaGetSymbolAddress((void**)&k, g_k);
    cudaGetSymbolAddress((void**)&v, g_v);
    cudaGetSymbolAddress((void**)&ctx, g_ctx);

    // Projections (tf32 tensor cores)
    gemm_tf32<128, 128><<<dim3(HDIM / 128, MTOT / 128), 256>>>(
        query, Wq, bq, q, MTOT, HDIM, IDIM);
    gemm_tf32<128, 64><<<dim3(1, MTOT / 128), 256>>>(
        key, Wk, bk, k, MTOT, DHEAD, IDIM);
    gemm_tf32<128, 64><<<dim3(1, MTOT / 128), 256>>>(
        value, Wv, bv, v, MTOT, DHEAD, IDIM);

    // Attention (tensor cores)
    mqa_attn_tc<<<dim3(SEQ / 64, NHEADS, BATCH), 128>>>(q, k, v, ctx);

    // Output projection -> d_out
    gemm_tf32<128, 128><<<dim3(IDIM / 128, MTOT / 128), 256>>>(
        ctx, Wo, bo, out, MTOT, IDIM, HDIM);
}

// round 7
// speedup vs baseline: 5.8342x; 2.7955x over previous
#include <cuda_runtime.h>
#include <cuda_fp16.h>
#include <cstdint>

#define IDIM   1024
#define HDIM   1024
#define NHEADS 16
#define DHEAD  64
#define BATCH  2
#define SEQ    2048
#define MTOT   (BATCH * SEQ)   // 4096

// Scratch (allocation-free rule: __device__ globals)
__device__ float g_q[(size_t)MTOT * HDIM];    // 16 MB
__device__ float g_k[(size_t)MTOT * DHEAD];   // 1 MB
__device__ float g_v[(size_t)MTOT * DHEAD];   // 1 MB
__device__ float g_ctx[(size_t)MTOT * HDIM];  // 16 MB

__device__ __forceinline__ uint32_t smem_u32(const void* p) {
    return static_cast<uint32_t>(__cvta_generic_to_shared(p));
}

__device__ __forceinline__ uint32_t h2pack(float a, float b) {
    __half2 h = __floats2half2_rn(a, b);
    return *reinterpret_cast<uint32_t*>(&h);
}

// D += A(16x16) * B(16x8), fp16 in / fp32 accum.
// A frag (4 regs, packed pairs): a0=(g,2t|2t+1) a1=(g+8,2t|2t+1) a2=(g,2t+8|2t+9) a3=(g+8,2t+8|2t+9)
// B frag (2 regs): b0=(k=2t|2t+1, n=g) b1=(k=2t+8|2t+9, n=g)
// C frag: c0=(g,2t) c1=(g,2t+1) c2=(g+8,2t) c3=(g+8,2t+1)     [g=lane/4, t=lane%4]
__device__ __forceinline__ void mma16816(float (&d)[4], const uint32_t (&a)[4],
                                         const uint32_t (&b)[2]) {
    asm volatile(
        "mma.sync.aligned.m16n8k16.row.col.f32.f16.f16.f32 "
        "{%0,%1,%2,%3}, {%4,%5,%6,%7}, {%8,%9}, {%0,%1,%2,%3};"
        : "+f"(d[0]), "+f"(d[1]), "+f"(d[2]), "+f"(d[3])
        : "r"(a[0]), "r"(a[1]), "r"(a[2]), "r"(a[3]), "r"(b[0]), "r"(b[1]));
}

__device__ __forceinline__ void ldsm4(uint32_t& r0, uint32_t& r1, uint32_t& r2,
                                      uint32_t& r3, uint32_t a) {
    asm volatile("ldmatrix.sync.aligned.m8n8.x4.shared.b16 {%0,%1,%2,%3}, [%4];"
                 : "=r"(r0), "=r"(r1), "=r"(r2), "=r"(r3) : "r"(a));
}
__device__ __forceinline__ void ldsm4t(uint32_t& r0, uint32_t& r1, uint32_t& r2,
                                       uint32_t& r3, uint32_t a) {
    asm volatile("ldmatrix.sync.aligned.m8n8.x4.trans.shared.b16 {%0,%1,%2,%3}, [%4];"
                 : "=r"(r0), "=r"(r1), "=r"(r2), "=r"(r3) : "r"(a));
}

// ---------------------------------------------------------------------------
// fp16 tensor-core GEMM: C[M,N] = A[M,K] @ W[K,N] + bias[N], fp32 accumulate.
// 256 thr = 8 warps (2x4). BM x BN x 32 tile, double-buffered smem, f32->f16
// convert on smem store. A stored [m][k] (64B rows, swizzle ch^((r>>1)&3)),
// W stored [k][n] (2*BN B rows, swizzle ch^(r&7)); frags via ldmatrix(.trans).
// ---------------------------------------------------------------------------
template <int BM, int BN>
__global__ void __launch_bounds__(256)
gemm_f16(const float* __restrict__ A, const float* __restrict__ W,
         const float* __restrict__ bias, float* __restrict__ C,
         int M, int N, int K)
{
    constexpr int BK    = 32;
    constexpr int MT    = (BM / 2) / 16;
    constexpr int NT    = (BN / 4) / 8;
    constexpr int APF   = BM / 32;      // float4 loads per thread (A)
    constexpr int WPF   = BN / 32;      // float4 loads per thread (W)
    constexpr int WROWB = BN * 2;       // Ws row bytes

    __shared__ __align__(16) uint8_t sA[2][BM * 64];
    __shared__ __align__(16) uint8_t sW[2][BK * WROWB];

    const int tid  = threadIdx.x;
    const int lane = tid & 31;
    const int warp = tid >> 5;
    const int wm   = warp >> 2;
    const int wn   = warp & 3;
    const int m0   = blockIdx.y * BM;
    const int n0   = blockIdx.x * BN;

    float acc[MT][NT][4];
#pragma unroll
    for (int i = 0; i < MT; i++)
#pragma unroll
        for (int j = 0; j < NT; j++)
#pragma unroll
            for (int e = 0; e < 4; e++) acc[i][j][e] = 0.f;

    // ---- stage 0 fill ----
#pragma unroll
    for (int i = 0; i < APF; i++) {
        int idx = tid + i * 256;
        int row = idx >> 3, j = idx & 7;
        float4 v = *reinterpret_cast<const float4*>(&A[(size_t)(m0 + row) * K + j * 4]);
        uint2 hh = { h2pack(v.x, v.y), h2pack(v.z, v.w) };
        *reinterpret_cast<uint2*>(
            &sA[0][row * 64 + (((j >> 1) ^ ((row >> 1) & 3)) << 4) + ((j & 1) << 3)]) = hh;
    }
#pragma unroll
    for (int i = 0; i < WPF; i++) {
        int idx = tid + i * 256;
        int row = idx / (BN / 4), j = idx % (BN / 4);
        float4 v = *reinterpret_cast<const float4*>(&W[(size_t)row * N + n0 + j * 4]);
        uint2 hh = { h2pack(v.x, v.y), h2pack(v.z, v.w) };
        *reinterpret_cast<uint2*>(
            &sW[0][row * WROWB + (((j >> 1) ^ (row & 7)) << 4) + ((j & 1) << 3)]) = hh;
    }
    __syncthreads();

    const int NITER = K / BK;
    for (int t = 0; t < NITER; t++) {
        const int s = t & 1;

        float4 pfa[APF], pfw[WPF];
        if (t + 1 < NITER) {
            const int kk = (t + 1) * BK;
#pragma unroll
            for (int i = 0; i < APF; i++) {
                int idx = tid + i * 256;
                int row = idx >> 3, j = idx & 7;
                pfa[i] = *reinterpret_cast<const float4*>(
                    &A[(size_t)(m0 + row) * K + kk + j * 4]);
            }
#pragma unroll
            for (int i = 0; i < WPF; i++) {
                int idx = tid + i * 256;
                int row = idx / (BN / 4), j = idx % (BN / 4);
                pfw[i] = *reinterpret_cast<const float4*>(
                    &W[(size_t)(kk + row) * N + n0 + j * 4]);
            }
        }

        // compute: 2 k-steps of 16
#pragma unroll
        for (int ks = 0; ks < 2; ks++) {
            const int c0 = ks * 16;
            uint32_t af[MT][4];
#pragma unroll
            for (int mi = 0; mi < MT; mi++) {
                int row = wm * (BM / 2) + mi * 16 + (lane & 15);
                int hc = c0 + ((lane >> 4) << 3);
                ldsm4(af[mi][0], af[mi][1], af[mi][2], af[mi][3],
                      smem_u32(&sA[s][row * 64 + (((hc >> 3) ^ ((row >> 1) & 3)) << 4)]));
            }
#pragma unroll
            for (int np = 0; np < NT / 2; np++) {
                int nb = wn * (BN / 4) + np * 16;
                int kr = c0 + (lane & 15);
                int nc = nb + ((lane >> 4) << 3);
                uint32_t b0, b1, b2, b3;
                ldsm4t(b0, b1, b2, b3,
                       smem_u32(&sW[s][kr * WROWB + (((nc >> 3) ^ (kr & 7)) << 4)]));
                uint32_t bf0[2] = { b0, b1 }, bf1[2] = { b2, b3 };
#pragma unroll
                for (int mi = 0; mi < MT; mi++) {
                    mma16816(acc[mi][2 * np + 0], af[mi], bf0);
                    mma16816(acc[mi][2 * np + 1], af[mi], bf1);
                }
            }
        }

        if (t + 1 < NITER) {
            const int d = s ^ 1;
#pragma unroll
            for (int i = 0; i < APF; i++) {
                int idx = tid + i * 256;
                int row = idx >> 3, j = idx & 7;
                uint2 hh = { h2pack(pfa[i].x, pfa[i].y), h2pack(pfa[i].z, pfa[i].w) };
                *reinterpret_cast<uint2*>(
                    &sA[d][row * 64 + (((j >> 1) ^ ((row >> 1) & 3)) << 4) + ((j & 1) << 3)]) = hh;
            }
#pragma unroll
            for (int i = 0; i < WPF; i++) {
                int idx = tid + i * 256;
                int row = idx / (BN / 4), j = idx % (BN / 4);
                uint2 hh = { h2pack(pfw[i].x, pfw[i].y), h2pack(pfw[i].z, pfw[i].w) };
                *reinterpret_cast<uint2*>(
                    &sW[d][row * WROWB + (((j >> 1) ^ (row & 7)) << 4) + ((j & 1) << 3)]) = hh;
            }
        }
        __syncthreads();
    }

    // epilogue: bias + store
#pragma unroll
    for (int mi = 0; mi < MT; mi++) {
        int row = m0 + wm * (BM / 2) + mi * 16 + (lane >> 2);
#pragma unroll
        for (int ni = 0; ni < NT; ni++) {
            int col = n0 + wn * (BN / 4) + ni * 8 + 2 * (lane & 3);
            float b0 = bias[col], b1 = bias[col + 1];
            float2 v0 = make_float2(acc[mi][ni][0] + b0, acc[mi][ni][1] + b1);
            float2 v1 = make_float2(acc[mi][ni][2] + b0, acc[mi][ni][3] + b1);
            *reinterpret_cast<float2*>(&C[(size_t)row * N + col]) = v0;
            *reinterpret_cast<float2*>(&C[(size_t)(row + 8) * N + col]) = v1;
        }
    }
}

// ---------------------------------------------------------------------------
// fp16 tensor-core MQA flash attention. Block = (b, h, 64-q-tile), 128 thr.
// Warp owns 16 q rows. K/V streamed in 64-key tiles, fp16 in swizzled smem
// (128B rows, chunk ^= row&7). Q frags preloaded to registers; S and P live
// entirely in registers (C-frag -> A-frag repack); all smem reads = ldmatrix.
// ---------------------------------------------------------------------------
__global__ void __launch_bounds__(128)
mqa_attn_f16(const float* __restrict__ Qp, const float* __restrict__ Kp,
             const float* __restrict__ Vp, float* __restrict__ ctx)
{
    __shared__ __align__(16) uint8_t sQ[64 * 128];
    __shared__ __align__(16) uint8_t sK[64 * 128];
    __shared__ __align__(16) uint8_t sV[64 * 128];

    const int tid  = threadIdx.x;
    const int lane = tid & 31;
    const int warp = tid >> 5;
    const int b    = blockIdx.z;
    const int h    = blockIdx.y;
    const int q0   = blockIdx.x * 64;
    const int g    = lane >> 2;
    const int tq   = lane & 3;

    // Load + pre-scale Q (2^-5 exact), convert to fp16 swizzled
    {
        const float* qb = Qp + (size_t)(b * SEQ + q0) * HDIM + h * DHEAD;
        for (int i = tid; i < 1024; i += 128) {
            int r = i >> 4, j = i & 15;
            float4 v = *reinterpret_cast<const float4*>(&qb[(size_t)r * HDIM + j * 4]);
            uint2 hh = { h2pack(v.x * 0.03125f, v.y * 0.03125f),
                         h2pack(v.z * 0.03125f, v.w * 0.03125f) };
            *reinterpret_cast<uint2*>(
                &sQ[r * 128 + (((j >> 1) ^ (r & 7)) << 4) + ((j & 1) << 3)]) = hh;
        }
    }
    __syncthreads();

    // Preload Q fragments (m16 x k64 per warp) into registers
    uint32_t qa[4][4];
#pragma unroll
    for (int ks = 0; ks < 4; ks++) {
        int row = warp * 16 + (lane & 15);
        int hc = ks * 16 + ((lane >> 4) << 3);
        ldsm4(qa[ks][0], qa[ks][1], qa[ks][2], qa[ks][3],
              smem_u32(&sQ[row * 128 + (((hc >> 3) ^ (row & 7)) << 4)]));
    }

    float m2[2] = { -1e30f, -1e30f };
    float l2[2] = { 0.f, 0.f };
    float o[8][4];
#pragma unroll
    for (int i = 0; i < 8; i++)
#pragma unroll
        for (int j = 0; j < 4; j++) o[i][j] = 0.f;

    const float* kg = Kp + (size_t)b * SEQ * DHEAD;
    const float* vg = Vp + (size_t)b * SEQ * DHEAD;

    for (int kt = 0; kt < SEQ; kt += 64) {
        // load K/V 64-key tiles (fp16 convert, swizzled)
        for (int i = tid; i < 1024; i += 128) {
            int r = i >> 4, j = i & 15;
            float4 kv = *reinterpret_cast<const float4*>(&kg[(size_t)(kt + r) * DHEAD + j * 4]);
            float4 vv = *reinterpret_cast<const float4*>(&vg[(size_t)(kt + r) * DHEAD + j * 4]);
            int off = r * 128 + (((j >> 1) ^ (r & 7)) << 4) + ((j & 1) << 3);
            *reinterpret_cast<uint2*>(&sK[off]) = { h2pack(kv.x, kv.y), h2pack(kv.z, kv.w) };
            *reinterpret_cast<uint2*>(&sV[off]) = { h2pack(vv.x, vv.y), h2pack(vv.z, vv.w) };
        }
        __syncthreads();

        // S = Q @ K^T : m16 x n64 x k64
        float s[8][4];
#pragma unroll
        for (int nt = 0; nt < 8; nt++)
#pragma unroll
            for (int e = 0; e < 4; e++) s[nt][e] = 0.f;

#pragma unroll
        for (int ks = 0; ks < 4; ks++) {
#pragma unroll
            for (int np = 0; np < 4; np++) {
                int nr = np * 16 + (lane & 7) + ((lane >> 4) << 3);
                int hc = ks * 16 + (((lane >> 3) & 1) << 3);
                uint32_t k0, k1, k2, k3;
                ldsm4(k0, k1, k2, k3,
                      smem_u32(&sK[nr * 128 + (((hc >> 3) ^ (nr & 7)) << 4)]));
                uint32_t bf0[2] = { k0, k1 }, bf1[2] = { k2, k3 };
                mma16816(s[2 * np + 0], qa[ks], bf0);
                mma16816(s[2 * np + 1], qa[ks], bf1);
            }
        }

        // online softmax (rows g / g+8), all in registers
        float mx0 = -1e30f, mx1 = -1e30f;
#pragma unroll
        for (int nt = 0; nt < 8; nt++) {
            mx0 = fmaxf(mx0, fmaxf(s[nt][0], s[nt][1]));
            mx1 = fmaxf(mx1, fmaxf(s[nt][2], s[nt][3]));
        }
        mx0 = fmaxf(mx0, __shfl_xor_sync(0xffffffffu, mx0, 1));
        mx0 = fmaxf(mx0, __shfl_xor_sync(0xffffffffu, mx0, 2));
        mx1 = fmaxf(mx1, __shfl_xor_sync(0xffffffffu, mx1, 1));
        mx1 = fmaxf(mx1, __shfl_xor_sync(0xffffffffu, mx1, 2));

        float mn0 = fmaxf(m2[0], mx0), mn1 = fmaxf(m2[1], mx1);
        float f0 = __expf(m2[0] - mn0), f1 = __expf(m2[1] - mn1);
        m2[0] = mn0; m2[1] = mn1;

        float sum0 = 0.f, sum1 = 0.f;
#pragma unroll
        for (int nt = 0; nt < 8; nt++) {
            s[nt][0] = __expf(s[nt][0] - mn0);
            s[nt][1] = __expf(s[nt][1] - mn0);
            s[nt][2] = __expf(s[nt][2] - mn1);
            s[nt][3] = __expf(s[nt][3] - mn1);
            sum0 += s[nt][0] + s[nt][1];
            sum1 += s[nt][2] + s[nt][3];
        }
        sum0 += __shfl_xor_sync(0xffffffffu, sum0, 1);
        sum0 += __shfl_xor_sync(0xffffffffu, sum0, 2);
        sum1 += __shfl_xor_sync(0xffffffffu, sum1, 1);
        sum1 += __shfl_xor_sync(0xffffffffu, sum1, 2);
        l2[0] = l2[0] * f0 + sum0;
        l2[1] = l2[1] * f1 + sum1;

#pragma unroll
        for (int nt = 0; nt < 8; nt++) {
            o[nt][0] *= f0; o[nt][1] *= f0;
            o[nt][2] *= f1; o[nt][3] *= f1;
        }

        // P C-frag -> A-frag repack (registers only)
        uint32_t pa[4][4];
#pragma unroll
        for (int j = 0; j < 4; j++) {
            pa[j][0] = h2pack(s[2 * j + 0][0], s[2 * j + 0][1]);
            pa[j][1] = h2pack(s[2 * j + 0][2], s[2 * j + 0][3]);
            pa[j][2] = h2pack(s[2 * j + 1][0], s[2 * j + 1][1]);
            pa[j][3] = h2pack(s[2 * j + 1][2], s[2 * j + 1][3]);
        }

        // O += P @ V : m16 x n64(dims) x k64(keys), V via ldmatrix.trans
#pragma unroll
        for (int j = 0; j < 4; j++) {
#pragma unroll
            for (int np = 0; np < 4; np++) {
                int kr = j * 16 + (lane & 7) + (((lane >> 3) & 1) << 3);
                int dc = np * 16 + ((lane >> 4) << 3);
                uint32_t v0, v1, v2, v3;
                ldsm4t(v0, v1, v2, v3,
                       smem_u32(&sV[kr * 128 + (((dc >> 3) ^ (kr & 7)) << 4)]));
                uint32_t bf0[2] = { v0, v1 }, bf1[2] = { v2, v3 };
                mma16816(o[2 * np + 0], pa[j], bf0);
                mma16816(o[2 * np + 1], pa[j], bf1);
            }
        }
        __syncthreads();
    }

    // finalize
    const float inv0 = 1.f / l2[0];
    const float inv1 = 1.f / l2[1];
    const int grow = b * SEQ + q0 + warp * 16 + g;
#pragma unroll
    for (int nt = 0; nt < 8; nt++) {
        int col = h * DHEAD + nt * 8 + 2 * tq;
        float2 v0 = make_float2(o[nt][0] * inv0, o[nt][1] * inv0);
        float2 v1 = make_float2(o[nt][2] * inv1, o[nt][3] * inv1);
        *reinterpret_cast<float2*>(&ctx[(size_t)grow * HDIM + col]) = v0;
        *reinterpret_cast<float2*>(&ctx[(size_t)(grow + 8) * HDIM + col]) = v1;
    }
}

// ---------------------------------------------------------------------------
extern "C" void kernel_launch(void* const* d_in, const int* in_sizes, int n_in,
                              void* d_out, int out_size)
{
    const float* query = (const float*)d_in[0];
    const float* key   = (const float*)d_in[1];
    const float* value = (const float*)d_in[2];
    const float* Wq    = (const float*)d_in[3];
    const float* bq    = (const float*)d_in[4];
    const float* Wk    = (const float*)d_in[5];
    const float* bk    = (const float*)d_in[6];
    const float* Wv    = (const float*)d_in[7];
    const float* bv    = (const float*)d_in[8];
    const float* Wo    = (const float*)d_in[9];
    const float* bo    = (const float*)d_in[10];
    float* out = (float*)d_out;

    float *q, *k, *v, *ctx;
    cudaGetSymbolAddress((void**)&q, g_q);
    cudaGetSymbolAddress((void**)&k, g_k);
    cudaGetSymbolAddress((void**)&v, g_v);
    cudaGetSymbolAddress((void**)&ctx, g_ctx);

    // Projections (fp16 tensor cores, fp32 accumulate)
    gemm_f16<128, 128><<<dim3(HDIM / 128, MTOT / 128), 256>>>(
        query, Wq, bq, q, MTOT, HDIM, IDIM);
    gemm_f16<64, 64><<<dim3(1, MTOT / 64), 256>>>(
        key, Wk, bk, k, MTOT, DHEAD, IDIM);
    gemm_f16<64, 64><<<dim3(1, MTOT / 64), 256>>>(
        value, Wv, bv, v, MTOT, DHEAD, IDIM);

    // Attention (fp16 tensor cores)
    mqa_attn_f16<<<dim3(SEQ / 64, NHEADS, BATCH), 128>>>(q, k, v, ctx);

    // Output projection -> d_out
    gemm_f16<128, 128><<<dim3(IDIM / 128, MTOT / 128), 256>>>(
        ctx, Wo, bo, out, MTOT, IDIM, HDIM);
}

// round 8
// speedup vs baseline: 6.4852x; 1.1116x over previous
#include <cuda_runtime.h>
#include <cuda_fp16.h>
#include <cstdint>

#define IDIM   1024
#define HDIM   1024
#define NHEADS 16
#define DHEAD  64
#define BATCH  2
#define SEQ    2048
#define MTOT   (BATCH * SEQ)   // 4096

// log2(e) / sqrt(HIDDEN_DIM) folded into the Q projection epilogue
#define QSCALE 0.04508422002570063f

// Scratch (allocation-free rule: __device__ globals), fp16 end-to-end
__device__ __half g_qh[(size_t)MTOT * HDIM];    // 8 MB
__device__ __half g_kh[(size_t)MTOT * DHEAD];   // 0.5 MB
__device__ __half g_vh[(size_t)MTOT * DHEAD];   // 0.5 MB
__device__ __half g_ctxh[(size_t)MTOT * HDIM];  // 8 MB

__device__ __forceinline__ uint32_t smem_u32(const void* p) {
    return static_cast<uint32_t>(__cvta_generic_to_shared(p));
}
__device__ __forceinline__ uint32_t h2pack(float a, float b) {
    __half2 h = __floats2half2_rn(a, b);
    return *reinterpret_cast<uint32_t*>(&h);
}
__device__ __forceinline__ float ex2(float x) {
    float y;
    asm("ex2.approx.ftz.f32 %0, %1;" : "=f"(y) : "f"(x));
    return y;
}
__device__ __forceinline__ void cp16(uint32_t dst, const void* src) {
    asm volatile("cp.async.cg.shared.global [%0], [%1], 16;" :: "r"(dst), "l"(src));
}
#define CP_COMMIT() asm volatile("cp.async.commit_group;")
template <int N>
__device__ __forceinline__ void cp_wait() {
    asm volatile("cp.async.wait_group %0;" :: "n"(N));
}

// D += A(16x16) * B(16x8), fp16 in / fp32 accum.
__device__ __forceinline__ void mma16816(float (&d)[4], const uint32_t (&a)[4],
                                         const uint32_t (&b)[2]) {
    asm volatile(
        "mma.sync.aligned.m16n8k16.row.col.f32.f16.f16.f32 "
        "{%0,%1,%2,%3}, {%4,%5,%6,%7}, {%8,%9}, {%0,%1,%2,%3};"
        : "+f"(d[0]), "+f"(d[1]), "+f"(d[2]), "+f"(d[3])
        : "r"(a[0]), "r"(a[1]), "r"(a[2]), "r"(a[3]), "r"(b[0]), "r"(b[1]));
}
__device__ __forceinline__ void ldsm4(uint32_t& r0, uint32_t& r1, uint32_t& r2,
                                      uint32_t& r3, uint32_t a) {
    asm volatile("ldmatrix.sync.aligned.m8n8.x4.shared.b16 {%0,%1,%2,%3}, [%4];"
                 : "=r"(r0), "=r"(r1), "=r"(r2), "=r"(r3) : "r"(a));
}
__device__ __forceinline__ void ldsm4t(uint32_t& r0, uint32_t& r1, uint32_t& r2,
                                       uint32_t& r3, uint32_t a) {
    asm volatile("ldmatrix.sync.aligned.m8n8.x4.trans.shared.b16 {%0,%1,%2,%3}, [%4];"
                 : "=r"(r0), "=r"(r1), "=r"(r2), "=r"(r3) : "r"(a));
}

// ---------------------------------------------------------------------------
// fp16 tensor-core GEMM: C = A @ W + bias, optional fp16 A (cp.async path),
// optional fp16 C, epilogue scale. 256 thr = 8 warps (2x4), BMxBNx32 tiles,
// double-buffered swizzled smem, ldmatrix fragments.
// ---------------------------------------------------------------------------
template <int BM, int BN, bool AHALF, bool OHALF>
__global__ void __launch_bounds__(256)
gemm_f16(const void* __restrict__ Ap, const float* __restrict__ W,
         const float* __restrict__ bias, void* __restrict__ Cp,
         int M, int N, int K, float oscale)
{
    constexpr int BK    = 32;
    constexpr int MT    = (BM / 2) / 16;
    constexpr int NT    = (BN / 4) / 8;
    constexpr int APF   = BM / 32;      // fp32-A: float4 loads per thread
    constexpr int ACH   = BM / 64;      // fp16-A: 16B chunks per thread
    constexpr int WPF   = BN / 32;
    constexpr int WROWB = BN * 2;

    __shared__ __align__(16) uint8_t sA[2][BM * 64];
    __shared__ __align__(16) uint8_t sW[2][BK * WROWB];

    const float*  Af = (const float*)Ap;
    const __half* Ah = (const __half*)Ap;
    float*  Cf = (float*)Cp;
    __half* Ch = (__half*)Cp;

    const int tid  = threadIdx.x;
    const int lane = tid & 31;
    const int warp = tid >> 5;
    const int wm   = warp >> 2;
    const int wn   = warp & 3;
    const int m0   = blockIdx.y * BM;
    const int n0   = blockIdx.x * BN;

    float acc[MT][NT][4];
#pragma unroll
    for (int i = 0; i < MT; i++)
#pragma unroll
        for (int j = 0; j < NT; j++)
#pragma unroll
            for (int e = 0; e < 4; e++) acc[i][j][e] = 0.f;

    // ---- stage 0 fill ----
    if (AHALF) {
#pragma unroll
        for (int i = 0; i < ACH; i++) {
            int idx = tid + i * 256;
            int row = idx >> 2, c = idx & 3;
            cp16(smem_u32(&sA[0][row * 64 + ((c ^ ((row >> 1) & 3)) << 4)]),
                 Ah + (size_t)(m0 + row) * K + c * 8);
        }
        CP_COMMIT();
    } else {
#pragma unroll
        for (int i = 0; i < APF; i++) {
            int idx = tid + i * 256;
            int row = idx >> 3, j = idx & 7;
            float4 v = *reinterpret_cast<const float4*>(&Af[(size_t)(m0 + row) * K + j * 4]);
            uint2 hh = { h2pack(v.x, v.y), h2pack(v.z, v.w) };
            *reinterpret_cast<uint2*>(
                &sA[0][row * 64 + (((j >> 1) ^ ((row >> 1) & 3)) << 4) + ((j & 1) << 3)]) = hh;
        }
    }
#pragma unroll
    for (int i = 0; i < WPF; i++) {
        int idx = tid + i * 256;
        int row = idx / (BN / 4), j = idx % (BN / 4);
        float4 v = *reinterpret_cast<const float4*>(&W[(size_t)row * N + n0 + j * 4]);
        uint2 hh = { h2pack(v.x, v.y), h2pack(v.z, v.w) };
        *reinterpret_cast<uint2*>(
            &sW[0][row * WROWB + (((j >> 1) ^ (row & 7)) << 4) + ((j & 1) << 3)]) = hh;
    }
    if (AHALF) cp_wait<0>();
    __syncthreads();

    const int NITER = K / BK;
    for (int t = 0; t < NITER; t++) {
        const int s = t & 1;
        const int d = s ^ 1;

        float4 pfa[AHALF ? 1 : APF], pfw[WPF];
        if (t + 1 < NITER) {
            const int kk = (t + 1) * BK;
            if (AHALF) {
#pragma unroll
                for (int i = 0; i < ACH; i++) {
                    int idx = tid + i * 256;
                    int row = idx >> 2, c = idx & 3;
                    cp16(smem_u32(&sA[d][row * 64 + ((c ^ ((row >> 1) & 3)) << 4)]),
                         Ah + (size_t)(m0 + row) * K + kk + c * 8);
                }
                CP_COMMIT();
            } else {
#pragma unroll
                for (int i = 0; i < APF; i++) {
                    int idx = tid + i * 256;
                    int row = idx >> 3, j = idx & 7;
                    pfa[i] = *reinterpret_cast<const float4*>(
                        &Af[(size_t)(m0 + row) * K + kk + j * 4]);
                }
            }
#pragma unroll
            for (int i = 0; i < WPF; i++) {
                int idx = tid + i * 256;
                int row = idx / (BN / 4), j = idx % (BN / 4);
                pfw[i] = *reinterpret_cast<const float4*>(
                    &W[(size_t)(kk + row) * N + n0 + j * 4]);
            }
        }

        // compute: 2 k-steps of 16
#pragma unroll
        for (int ks = 0; ks < 2; ks++) {
            const int c0 = ks * 16;
            uint32_t af[MT][4];
#pragma unroll
            for (int mi = 0; mi < MT; mi++) {
                int row = wm * (BM / 2) + mi * 16 + (lane & 15);
                int hc = c0 + ((lane >> 4) << 3);
                ldsm4(af[mi][0], af[mi][1], af[mi][2], af[mi][3],
                      smem_u32(&sA[s][row * 64 + (((hc >> 3) ^ ((row >> 1) & 3)) << 4)]));
            }
#pragma unroll
            for (int np = 0; np < NT / 2; np++) {
                int nb = wn * (BN / 4) + np * 16;
                int kr = c0 + (lane & 15);
                int nc = nb + ((lane >> 4) << 3);
                uint32_t b0, b1, b2, b3;
                ldsm4t(b0, b1, b2, b3,
                       smem_u32(&sW[s][kr * WROWB + (((nc >> 3) ^ (kr & 7)) << 4)]));
                uint32_t bf0[2] = { b0, b1 }, bf1[2] = { b2, b3 };
#pragma unroll
                for (int mi = 0; mi < MT; mi++) {
                    mma16816(acc[mi][2 * np + 0], af[mi], bf0);
                    mma16816(acc[mi][2 * np + 1], af[mi], bf1);
                }
            }
        }

        if (t + 1 < NITER) {
            if (!AHALF) {
#pragma unroll
                for (int i = 0; i < APF; i++) {
                    int idx = tid + i * 256;
                    int row = idx >> 3, j = idx & 7;
                    uint2 hh = { h2pack(pfa[i].x, pfa[i].y), h2pack(pfa[i].z, pfa[i].w) };
                    *reinterpret_cast<uint2*>(
                        &sA[d][row * 64 + (((j >> 1) ^ ((row >> 1) & 3)) << 4) + ((j & 1) << 3)]) = hh;
                }
            }
#pragma unroll
            for (int i = 0; i < WPF; i++) {
                int idx = tid + i * 256;
                int row = idx / (BN / 4), j = idx % (BN / 4);
                uint2 hh = { h2pack(pfw[i].x, pfw[i].y), h2pack(pfw[i].z, pfw[i].w) };
                *reinterpret_cast<uint2*>(
                    &sW[d][row * WROWB + (((j >> 1) ^ (row & 7)) << 4) + ((j & 1) << 3)]) = hh;
            }
            if (AHALF) cp_wait<0>();
        }
        __syncthreads();
    }

    // epilogue: bias + scale + store
#pragma unroll
    for (int mi = 0; mi < MT; mi++) {
        int row = m0 + wm * (BM / 2) + mi * 16 + (lane >> 2);
#pragma unroll
        for (int ni = 0; ni < NT; ni++) {
            int col = n0 + wn * (BN / 4) + ni * 8 + 2 * (lane & 3);
            float b0 = bias[col], b1 = bias[col + 1];
            float v00 = (acc[mi][ni][0] + b0) * oscale;
            float v01 = (acc[mi][ni][1] + b1) * oscale;
            float v10 = (acc[mi][ni][2] + b0) * oscale;
            float v11 = (acc[mi][ni][3] + b1) * oscale;
            if (OHALF) {
                *reinterpret_cast<__half2*>(&Ch[(size_t)row * N + col]) =
                    __floats2half2_rn(v00, v01);
                *reinterpret_cast<__half2*>(&Ch[(size_t)(row + 8) * N + col]) =
                    __floats2half2_rn(v10, v11);
            } else {
                *reinterpret_cast<float2*>(&Cf[(size_t)row * N + col]) =
                    make_float2(v00, v01);
                *reinterpret_cast<float2*>(&Cf[(size_t)(row + 8) * N + col]) =
                    make_float2(v10, v11);
            }
        }
    }
}

// ---------------------------------------------------------------------------
// fp16 MQA flash attention, cp.async double-buffered K/V stream.
// Block = (b, h, 128-q-tile), 256 thr = 8 warps, warp owns 16 q rows.
// Q pre-scaled by log2e/32 in projection; softmax in base 2 (ex2.approx).
// smem 32KB: [0,16K) Q staging then K/V stage 1; [16K,24K) K0; [24K,32K) V0.
// ---------------------------------------------------------------------------
__global__ void __launch_bounds__(256)
mqa_attn_f16(const __half* __restrict__ Qh, const __half* __restrict__ Kh,
             const __half* __restrict__ Vh, __half* __restrict__ ctxh)
{
    __shared__ __align__(16) uint8_t smem[32768];
    const int OFF_K[2] = { 16384, 0 };
    const int OFF_V[2] = { 24576, 8192 };

    const int tid  = threadIdx.x;
    const int lane = tid & 31;
    const int warp = tid >> 5;
    const int b    = blockIdx.z;
    const int h    = blockIdx.y;
    const int q0   = blockIdx.x * 128;
    const int g    = lane >> 2;
    const int tq   = lane & 3;

    const __half* kg = Kh + (size_t)b * SEQ * DHEAD;
    const __half* vg = Vh + (size_t)b * SEQ * DHEAD;

    // Q staging (cp.async) + K/V tile 0, one group
    {
        const __half* qb = Qh + (size_t)(b * SEQ + q0) * HDIM + h * DHEAD;
#pragma unroll
        for (int i = 0; i < 4; i++) {
            int idx = tid + i * 256;
            int r = idx >> 3, c = idx & 7;
            cp16(smem_u32(&smem[r * 128 + ((c ^ (r & 7)) << 4)]),
                 qb + (size_t)r * HDIM + c * 8);
        }
#pragma unroll
        for (int i = 0; i < 2; i++) {
            int idx = tid + i * 256;
            int r = idx >> 3, c = idx & 7;
            int off = r * 128 + ((c ^ (r & 7)) << 4);
            cp16(smem_u32(&smem[OFF_K[0] + off]), kg + (size_t)r * DHEAD + c * 8);
            cp16(smem_u32(&smem[OFF_V[0] + off]), vg + (size_t)r * DHEAD + c * 8);
        }
        CP_COMMIT();
    }
    cp_wait<0>();
    __syncthreads();

    // Preload Q fragments (m16 x k64 per warp)
    uint32_t qa[4][4];
#pragma unroll
    for (int ks = 0; ks < 4; ks++) {
        int row = warp * 16 + (lane & 15);
        int hc = ks * 16 + ((lane >> 4) << 3);
        ldsm4(qa[ks][0], qa[ks][1], qa[ks][2], qa[ks][3],
              smem_u32(&smem[row * 128 + (((hc >> 3) ^ (row & 7)) << 4)]));
    }
    __syncthreads();   // Q region free for stage-1 K/V

    float m2[2] = { -1e30f, -1e30f };
    float l2[2] = { 0.f, 0.f };
    float o[8][4];
#pragma unroll
    for (int i = 0; i < 8; i++)
#pragma unroll
        for (int j = 0; j < 4; j++) o[i][j] = 0.f;

    const int NT_KV = SEQ / 64;
    for (int t = 0; t < NT_KV; t++) {
        const int s = t & 1;

        if (t + 1 < NT_KV) {
            const int kt = (t + 1) * 64;
#pragma unroll
            for (int i = 0; i < 2; i++) {
                int idx = tid + i * 256;
                int r = idx >> 3, c = idx & 7;
                int off = r * 128 + ((c ^ (r & 7)) << 4);
                cp16(smem_u32(&smem[OFF_K[s ^ 1] + off]),
                     kg + (size_t)(kt + r) * DHEAD + c * 8);
                cp16(smem_u32(&smem[OFF_V[s ^ 1] + off]),
                     vg + (size_t)(kt + r) * DHEAD + c * 8);
            }
            CP_COMMIT();
            cp_wait<1>();
        } else {
            cp_wait<0>();
        }
        __syncthreads();

        const uint8_t* sK = &smem[OFF_K[s]];
        const uint8_t* sV = &smem[OFF_V[s]];

        // S = Q @ K^T : m16 x n64 x k64 (scores already in log2 domain)
        float sc[8][4];
#pragma unroll
        for (int nt = 0; nt < 8; nt++)
#pragma unroll
            for (int e = 0; e < 4; e++) sc[nt][e] = 0.f;

#pragma unroll
        for (int ks = 0; ks < 4; ks++) {
#pragma unroll
            for (int np = 0; np < 4; np++) {
                int nr = np * 16 + (lane & 7) + ((lane >> 4) << 3);
                int hc = ks * 16 + (((lane >> 3) & 1) << 3);
                uint32_t k0, k1, k2, k3;
                ldsm4(k0, k1, k2, k3,
                      smem_u32(&sK[nr * 128 + (((hc >> 3) ^ (nr & 7)) << 4)]));
                uint32_t bf0[2] = { k0, k1 }, bf1[2] = { k2, k3 };
                mma16816(sc[2 * np + 0], qa[ks], bf0);
                mma16816(sc[2 * np + 1], qa[ks], bf1);
            }
        }

        // online softmax (base 2), rows g / g+8
        float mx0 = -1e30f, mx1 = -1e30f;
#pragma unroll
        for (int nt = 0; nt < 8; nt++) {
            mx0 = fmaxf(mx0, fmaxf(sc[nt][0], sc[nt][1]));
            mx1 = fmaxf(mx1, fmaxf(sc[nt][2], sc[nt][3]));
        }
        mx0 = fmaxf(mx0, __shfl_xor_sync(0xffffffffu, mx0, 1));
        mx0 = fmaxf(mx0, __shfl_xor_sync(0xffffffffu, mx0, 2));
        mx1 = fmaxf(mx1, __shfl_xor_sync(0xffffffffu, mx1, 1));
        mx1 = fmaxf(mx1, __shfl_xor_sync(0xffffffffu, mx1, 2));

        float mn0 = fmaxf(m2[0], mx0), mn1 = fmaxf(m2[1], mx1);
        float f0 = ex2(m2[0] - mn0), f1 = ex2(m2[1] - mn1);
        m2[0] = mn0; m2[1] = mn1;

        float sum0 = 0.f, sum1 = 0.f;
#pragma unroll
        for (int nt = 0; nt < 8; nt++) {
            sc[nt][0] = ex2(sc[nt][0] - mn0);
            sc[nt][1] = ex2(sc[nt][1] - mn0);
            sc[nt][2] = ex2(sc[nt][2] - mn1);
            sc[nt][3] = ex2(sc[nt][3] - mn1);
            sum0 += sc[nt][0] + sc[nt][1];
            sum1 += sc[nt][2] + sc[nt][3];
        }
        sum0 += __shfl_xor_sync(0xffffffffu, sum0, 1);
        sum0 += __shfl_xor_sync(0xffffffffu, sum0, 2);
        sum1 += __shfl_xor_sync(0xffffffffu, sum1, 1);
        sum1 += __shfl_xor_sync(0xffffffffu, sum1, 2);
        l2[0] = l2[0] * f0 + sum0;
        l2[1] = l2[1] * f1 + sum1;

#pragma unroll
        for (int nt = 0; nt < 8; nt++) {
            o[nt][0] *= f0; o[nt][1] *= f0;
            o[nt][2] *= f1; o[nt][3] *= f1;
        }

        // P C-frag -> A-frag repack (registers only)
        uint32_t pa[4][4];
#pragma unroll
        for (int j = 0; j < 4; j++) {
            pa[j][0] = h2pack(sc[2 * j + 0][0], sc[2 * j + 0][1]);
            pa[j][1] = h2pack(sc[2 * j + 0][2], sc[2 * j + 0][3]);
            pa[j][2] = h2pack(sc[2 * j + 1][0], sc[2 * j + 1][1]);
            pa[j][3] = h2pack(sc[2 * j + 1][2], sc[2 * j + 1][3]);
        }

        // O += P @ V, V via ldmatrix.trans
#pragma unroll
        for (int j = 0; j < 4; j++) {
#pragma unroll
            for (int np = 0; np < 4; np++) {
                int kr = j * 16 + (lane & 7) + (((lane >> 3) & 1) << 3);
                int dc = np * 16 + ((lane >> 4) << 3);
                uint32_t v0, v1, v2, v3;
                ldsm4t(v0, v1, v2, v3,
                       smem_u32(&sV[kr * 128 + (((dc >> 3) ^ (kr & 7)) << 4)]));
                uint32_t bf0[2] = { v0, v1 }, bf1[2] = { v2, v3 };
                mma16816(o[2 * np + 0], pa[j], bf0);
                mma16816(o[2 * np + 1], pa[j], bf1);
            }
        }
        __syncthreads();
    }

    // finalize: divide by l, write fp16 ctx
    const float inv0 = 1.f / l2[0];
    const float inv1 = 1.f / l2[1];
    const int grow = b * SEQ + q0 + warp * 16 + g;
#pragma unroll
    for (int nt = 0; nt < 8; nt++) {
        int col = h * DHEAD + nt * 8 + 2 * tq;
        *reinterpret_cast<__half2*>(&ctxh[(size_t)grow * HDIM + col]) =
            __floats2half2_rn(o[nt][0] * inv0, o[nt][1] * inv0);
        *reinterpret_cast<__half2*>(&ctxh[(size_t)(grow + 8) * HDIM + col]) =
            __floats2half2_rn(o[nt][2] * inv1, o[nt][3] * inv1);
    }
}

// ---------------------------------------------------------------------------
extern "C" void kernel_launch(void* const* d_in, const int* in_sizes, int n_in,
                              void* d_out, int out_size)
{
    const float* query = (const float*)d_in[0];
    const float* key   = (const float*)d_in[1];
    const float* value = (const float*)d_in[2];
    const float* Wq    = (const float*)d_in[3];
    const float* bq    = (const float*)d_in[4];
    const float* Wk    = (const float*)d_in[5];
    const float* bk    = (const float*)d_in[6];
    const float* Wv    = (const float*)d_in[7];
    const float* bv    = (const float*)d_in[8];
    const float* Wo    = (const float*)d_in[9];
    const float* bo    = (const float*)d_in[10];
    float* out = (float*)d_out;

    __half *qh, *kh, *vh, *ctxh;
    cudaGetSymbolAddress((void**)&qh, g_qh);
    cudaGetSymbolAddress((void**)&kh, g_kh);
    cudaGetSymbolAddress((void**)&vh, g_vh);
    cudaGetSymbolAddress((void**)&ctxh, g_ctxh);

    // Projections -> fp16 (Q pre-scaled into log2-softmax domain)
    gemm_f16<128, 128, false, true><<<dim3(HDIM / 128, MTOT / 128), 256>>>(
        query, Wq, bq, qh, MTOT, HDIM, IDIM, QSCALE);
    gemm_f16<64, 64, false, true><<<dim3(1, MTOT / 64), 256>>>(
        key, Wk, bk, kh, MTOT, DHEAD, IDIM, 1.0f);
    gemm_f16<64, 64, false, true><<<dim3(1, MTOT / 64), 256>>>(
        value, Wv, bv, vh, MTOT, DHEAD, IDIM, 1.0f);

    // Attention (fp16 in/out, cp.async double-buffered)
    mqa_attn_f16<<<dim3(SEQ / 128, NHEADS, BATCH), 256>>>(qh, kh, vh, ctxh);

    // Output projection: fp16 A -> fp32 out
    gemm_f16<128, 128, true, false><<<dim3(IDIM / 128, MTOT / 128), 256>>>(
        ctxh, Wo, bo, out, MTOT, IDIM, HDIM, 1.0f);
}

// round 15
// speedup vs baseline: 7.0921x; 1.0936x over previous
#include <cuda_runtime.h>
#include <cuda_fp16.h>
#include <cstdint>

#define IDIM   1024
#define HDIM   1024
#define NHEADS 16
#define DHEAD  64
#define BATCH  2
#define SEQ    2048
#define MTOT   (BATCH * SEQ)   // 4096

// log2(e) / sqrt(HIDDEN_DIM) folded into the Q projection epilogue
#define QSCALE 0.04508422002570063f

// Scratch (allocation-free rule: __device__ globals), fp16 end-to-end
__device__ __half g_qh[(size_t)MTOT * HDIM];     // 8 MB
__device__ __half g_kh[(size_t)MTOT * DHEAD];
__device__ __half g_vh[(size_t)MTOT * DHEAD];
__device__ __half g_ctxh[(size_t)MTOT * HDIM];   // 8 MB
// fp16 activations (converted once)
__device__ __half g_xq[(size_t)MTOT * IDIM];     // 8 MB
__device__ __half g_xk[(size_t)MTOT * IDIM];     // 8 MB
__device__ __half g_xv[(size_t)MTOT * IDIM];     // 8 MB
// fp16 transposed weights [N, K]
__device__ __half g_wqt[(size_t)HDIM * IDIM];    // 2 MB
__device__ __half g_wkt[(size_t)DHEAD * IDIM];
__device__ __half g_wvt[(size_t)DHEAD * IDIM];
__device__ __half g_wot[(size_t)IDIM * HDIM];    // 2 MB

__device__ __forceinline__ uint32_t smem_u32(const void* p) {
    return static_cast<uint32_t>(__cvta_generic_to_shared(p));
}
__device__ __forceinline__ uint32_t h2pack(float a, float b) {
    __half2 h = __floats2half2_rn(a, b);
    return *reinterpret_cast<uint32_t*>(&h);
}
__device__ __forceinline__ float ex2(float x) {
    float y;
    asm("ex2.approx.ftz.f32 %0, %1;" : "=f"(y) : "f"(x));
    return y;
}
__device__ __forceinline__ void cp16(uint32_t dst, const void* src) {
    asm volatile("cp.async.cg.shared.global [%0], [%1], 16;" :: "r"(dst), "l"(src));
}
#define CP_COMMIT() asm volatile("cp.async.commit_group;")
template <int N>
__device__ __forceinline__ void cp_wait() {
    asm volatile("cp.async.wait_group %0;" :: "n"(N));
}

// D += A(16x16) * B(16x8), fp16 in / fp32 accum.
__device__ __forceinline__ void mma16816(float (&d)[4], const uint32_t (&a)[4],
                                         const uint32_t (&b)[2]) {
    asm volatile(
        "mma.sync.aligned.m16n8k16.row.col.f32.f16.f16.f32 "
        "{%0,%1,%2,%3}, {%4,%5,%6,%7}, {%8,%9}, {%0,%1,%2,%3};"
        : "+f"(d[0]), "+f"(d[1]), "+f"(d[2]), "+f"(d[3])
        : "r"(a[0]), "r"(a[1]), "r"(a[2]), "r"(a[3]), "r"(b[0]), "r"(b[1]));
}
__device__ __forceinline__ void ldsm4(uint32_t& r0, uint32_t& r1, uint32_t& r2,
                                      uint32_t& r3, uint32_t a) {
    asm volatile("ldmatrix.sync.aligned.m8n8.x4.shared.b16 {%0,%1,%2,%3}, [%4];"
                 : "=r"(r0), "=r"(r1), "=r"(r2), "=r"(r3) : "r"(a));
}
__device__ __forceinline__ void ldsm4t(uint32_t& r0, uint32_t& r1, uint32_t& r2,
                                       uint32_t& r3, uint32_t a) {
    asm volatile("ldmatrix.sync.aligned.m8n8.x4.trans.shared.b16 {%0,%1,%2,%3}, [%4];"
                 : "=r"(r0), "=r"(r1), "=r"(r2), "=r"(r3) : "r"(a));
}

// ---------------------------------------------------------------------------
// Prep: fp32 -> fp16 activation convert (once per tensor)
// ---------------------------------------------------------------------------
__global__ void __launch_bounds__(256)
cvt_inputs(const float* __restrict__ q, const float* __restrict__ k,
           const float* __restrict__ v, __half* __restrict__ oq,
           __half* __restrict__ ok, __half* __restrict__ ov)
{
    const float* src = blockIdx.z == 0 ? q : (blockIdx.z == 1 ? k : v);
    __half* dst = blockIdx.z == 0 ? oq : (blockIdx.z == 1 ? ok : ov);
    size_t i = ((size_t)blockIdx.x * 256 + threadIdx.x) * 4;
    float4 x = *reinterpret_cast<const float4*>(src + i);
    uint2 hh = { h2pack(x.x, x.y), h2pack(x.z, x.w) };
    *reinterpret_cast<uint2*>(dst + i) = hh;
}

// Prep: W [K,N] fp32 -> Wt [N,K] fp16 (tiled transpose)
__global__ void __launch_bounds__(256)
transpose_w(const float* __restrict__ in, __half* __restrict__ out, int K, int N)
{
    __shared__ float t[32][33];
    int k0 = blockIdx.y * 32, n0 = blockIdx.x * 32;
    int tx = threadIdx.x & 31, ty = threadIdx.x >> 5;   // 32 x 8
#pragma unroll
    for (int i = 0; i < 4; i++)
        t[ty + 8 * i][tx] = in[(size_t)(k0 + ty + 8 * i) * N + n0 + tx];
    __syncthreads();
#pragma unroll
    for (int i = 0; i < 4; i++)
        out[(size_t)(n0 + ty + 8 * i) * K + k0 + tx] = __float2half(t[tx][ty + 8 * i]);
}

// ---------------------------------------------------------------------------
// fp16 fragment GEMM, both operands cp.async: C[M,N] = A[M,K] @ Bt[N,K]^T + b.
// A fp16 [M,K], Bt fp16 [N,K]. 256 thr = 8 warps (2x4), BMxBNx32 tiles,
// double-buffered 64B-row swizzled smem; A frags ldsm4, B frags ldsm4
// (non-trans, K-major rows like the attention K tile).
// ---------------------------------------------------------------------------
template <int BM, int BN, bool OHALF>
__global__ void __launch_bounds__(256)
gemm_f16h(const __half* __restrict__ A, const __half* __restrict__ Bt,
          const float* __restrict__ bias, void* __restrict__ Cp,
          int M, int N, int K, float oscale)
{
    constexpr int MT  = (BM / 2) / 16;
    constexpr int NT  = (BN / 4) / 8;
    constexpr int ACH = BM * 4 / 256;   // 16B chunks per thread per stage
    constexpr int WCH = BN * 4 / 256;

    __shared__ __align__(16) uint8_t sA[2][BM * 64];
    __shared__ __align__(16) uint8_t sW[2][BN * 64];

    const int tid  = threadIdx.x;
    const int lane = tid & 31;
    const int warp = tid >> 5;
    const int wm   = warp >> 2;
    const int wn   = warp & 3;
    const int m0   = blockIdx.y * BM;
    const int n0   = blockIdx.x * BN;

    float acc[MT][NT][4];
#pragma unroll
    for (int i = 0; i < MT; i++)
#pragma unroll
        for (int j = 0; j < NT; j++)
#pragma unroll
            for (int e = 0; e < 4; e++) acc[i][j][e] = 0.f;

    auto fill = [&](int s, int kk) {
#pragma unroll
        for (int i = 0; i < ACH; i++) {
            int idx = tid + i * 256;
            int r = idx >> 2, c = idx & 3;
            cp16(smem_u32(&sA[s][r * 64 + ((c ^ ((r >> 1) & 3)) << 4)]),
                 A + (size_t)(m0 + r) * K + kk + c * 8);
        }
#pragma unroll
        for (int i = 0; i < WCH; i++) {
            int idx = tid + i * 256;
            int r = idx >> 2, c = idx & 3;
            cp16(smem_u32(&sW[s][r * 64 + ((c ^ ((r >> 1) & 3)) << 4)]),
                 Bt + (size_t)(n0 + r) * K + kk + c * 8);
        }
        CP_COMMIT();
    };

    fill(0, 0);

    const int NITER = K / 32;
    for (int t = 0; t < NITER; t++) {
        const int s = t & 1;
        if (t + 1 < NITER) {
            fill(s ^ 1, (t + 1) * 32);   // buffer s^1 safe: sync at end of t-1
            cp_wait<1>();
        } else {
            cp_wait<0>();
        }
        __syncthreads();

        // 2 k-steps of 16
#pragma unroll
        for (int ks = 0; ks < 2; ks++) {
            const int c0 = ks * 16;
            uint32_t af[MT][4];
#pragma unroll
            for (int mi = 0; mi < MT; mi++) {
                int row = wm * (BM / 2) + mi * 16 + (lane & 15);
                int hc = c0 + ((lane >> 4) << 3);
                ldsm4(af[mi][0], af[mi][1], af[mi][2], af[mi][3],
                      smem_u32(&sA[s][row * 64 + (((hc >> 3) ^ ((row >> 1) & 3)) << 4)]));
            }
#pragma unroll
            for (int np = 0; np < NT / 2; np++) {
                int nr = wn * (BN / 4) + np * 16 + (lane & 7) + ((lane >> 4) << 3);
                int hc = c0 + (((lane >> 3) & 1) << 3);
                uint32_t b0, b1, b2, b3;
                ldsm4(b0, b1, b2, b3,
                      smem_u32(&sW[s][nr * 64 + (((hc >> 3) ^ ((nr >> 1) & 3)) << 4)]));
                uint32_t bf0[2] = { b0, b1 }, bf1[2] = { b2, b3 };
#pragma unroll
                for (int mi = 0; mi < MT; mi++) {
                    mma16816(acc[mi][2 * np + 0], af[mi], bf0);
                    mma16816(acc[mi][2 * np + 1], af[mi], bf1);
                }
            }
        }
        __syncthreads();
    }

    // epilogue: bias + scale + store
    float*  Cf = (float*)Cp;
    __half* Ch = (__half*)Cp;
#pragma unroll
    for (int mi = 0; mi < MT; mi++) {
        int row = m0 + wm * (BM / 2) + mi * 16 + (lane >> 2);
#pragma unroll
        for (int ni = 0; ni < NT; ni++) {
            int col = n0 + wn * (BN / 4) + ni * 8 + 2 * (lane & 3);
            float b0 = bias[col], b1 = bias[col + 1];
            float v00 = (acc[mi][ni][0] + b0) * oscale;
            float v01 = (acc[mi][ni][1] + b1) * oscale;
            float v10 = (acc[mi][ni][2] + b0) * oscale;
            float v11 = (acc[mi][ni][3] + b1) * oscale;
            if (OHALF) {
                *reinterpret_cast<__half2*>(&Ch[(size_t)row * N + col]) =
                    __floats2half2_rn(v00, v01);
                *reinterpret_cast<__half2*>(&Ch[(size_t)(row + 8) * N + col]) =
                    __floats2half2_rn(v10, v11);
            } else {
                *reinterpret_cast<float2*>(&Cf[(size_t)row * N + col]) =
                    make_float2(v00, v01);
                *reinterpret_cast<float2*>(&Cf[(size_t)(row + 8) * N + col]) =
                    make_float2(v10, v11);
            }
        }
    }
}

// ---------------------------------------------------------------------------
// fp16 MQA flash attention (round-8 validated version, unchanged).
// Block = (b, h, 128-q-tile), 256 thr = 8 warps, warp owns 16 q rows.
// Q pre-scaled by log2e/32 in projection; softmax in base 2 (ex2.approx).
// ---------------------------------------------------------------------------
__global__ void __launch_bounds__(256)
mqa_attn_f16(const __half* __restrict__ Qh, const __half* __restrict__ Kh,
             const __half* __restrict__ Vh, __half* __restrict__ ctxh)
{
    __shared__ __align__(16) uint8_t smem[32768];
    const int OFF_K[2] = { 16384, 0 };
    const int OFF_V[2] = { 24576, 8192 };

    const int tid  = threadIdx.x;
    const int lane = tid & 31;
    const int warp = tid >> 5;
    const int b    = blockIdx.z;
    const int h    = blockIdx.y;
    const int q0   = blockIdx.x * 128;
    const int g    = lane >> 2;
    const int tq   = lane & 3;

    const __half* kg = Kh + (size_t)b * SEQ * DHEAD;
    const __half* vg = Vh + (size_t)b * SEQ * DHEAD;

    {
        const __half* qb = Qh + (size_t)(b * SEQ + q0) * HDIM + h * DHEAD;
#pragma unroll
        for (int i = 0; i < 4; i++) {
            int idx = tid + i * 256;
            int r = idx >> 3, c = idx & 7;
            cp16(smem_u32(&smem[r * 128 + ((c ^ (r & 7)) << 4)]),
                 qb + (size_t)r * HDIM + c * 8);
        }
#pragma unroll
        for (int i = 0; i < 2; i++) {
            int idx = tid + i * 256;
            int r = idx >> 3, c = idx & 7;
            int off = r * 128 + ((c ^ (r & 7)) << 4);
            cp16(smem_u32(&smem[OFF_K[0] + off]), kg + (size_t)r * DHEAD + c * 8);
            cp16(smem_u32(&smem[OFF_V[0] + off]), vg + (size_t)r * DHEAD + c * 8);
        }
        CP_COMMIT();
    }
    cp_wait<0>();
    __syncthreads();

    uint32_t qa[4][4];
#pragma unroll
    for (int ks = 0; ks < 4; ks++) {
        int row = warp * 16 + (lane & 15);
        int hc = ks * 16 + ((lane >> 4) << 3);
        ldsm4(qa[ks][0], qa[ks][1], qa[ks][2], qa[ks][3],
              smem_u32(&smem[row * 128 + (((hc >> 3) ^ (row & 7)) << 4)]));
    }
    __syncthreads();

    float m2[2] = { -1e30f, -1e30f };
    float l2[2] = { 0.f, 0.f };
    float o[8][4];
#pragma unroll
    for (int i = 0; i < 8; i++)
#pragma unroll
        for (int j = 0; j < 4; j++) o[i][j] = 0.f;

    const int NT_KV = SEQ / 64;
    for (int t = 0; t < NT_KV; t++) {
        const int s = t & 1;

        if (t + 1 < NT_KV) {
            const int kt = (t + 1) * 64;
#pragma unroll
            for (int i = 0; i < 2; i++) {
                int idx = tid + i * 256;
                int r = idx >> 3, c = idx & 7;
                int off = r * 128 + ((c ^ (r & 7)) << 4);
                cp16(smem_u32(&smem[OFF_K[s ^ 1] + off]),
                     kg + (size_t)(kt + r) * DHEAD + c * 8);
                cp16(smem_u32(&smem[OFF_V[s ^ 1] + off]),
                     vg + (size_t)(kt + r) * DHEAD + c * 8);
            }
            CP_COMMIT();
            cp_wait<1>();
        } else {
            cp_wait<0>();
        }
        __syncthreads();

        const uint8_t* sK = &smem[OFF_K[s]];
        const uint8_t* sV = &smem[OFF_V[s]];

        float sc[8][4];
#pragma unroll
        for (int nt = 0; nt < 8; nt++)
#pragma unroll
            for (int e = 0; e < 4; e++) sc[nt][e] = 0.f;

#pragma unroll
        for (int ks = 0; ks < 4; ks++) {
#pragma unroll
            for (int np = 0; np < 4; np++) {
                int nr = np * 16 + (lane & 7) + ((lane >> 4) << 3);
                int hc = ks * 16 + (((lane >> 3) & 1) << 3);
                uint32_t k0, k1, k2, k3;
                ldsm4(k0, k1, k2, k3,
                      smem_u32(&sK[nr * 128 + (((hc >> 3) ^ (nr & 7)) << 4)]));
                uint32_t bf0[2] = { k0, k1 }, bf1[2] = { k2, k3 };
                mma16816(sc[2 * np + 0], qa[ks], bf0);
                mma16816(sc[2 * np + 1], qa[ks], bf1);
            }
        }

        float mx0 = -1e30f, mx1 = -1e30f;
#pragma unroll
        for (int nt = 0; nt < 8; nt++) {
            mx0 = fmaxf(mx0, fmaxf(sc[nt][0], sc[nt][1]));
            mx1 = fmaxf(mx1, fmaxf(sc[nt][2], sc[nt][3]));
        }
        mx0 = fmaxf(mx0, __shfl_xor_sync(0xffffffffu, mx0, 1));
        mx0 = fmaxf(mx0, __shfl_xor_sync(0xffffffffu, mx0, 2));
        mx1 = fmaxf(mx1, __shfl_xor_sync(0xffffffffu, mx1, 1));
        mx1 = fmaxf(mx1, __shfl_xor_sync(0xffffffffu, mx1, 2));

        float mn0 = fmaxf(m2[0], mx0), mn1 = fmaxf(m2[1], mx1);
        float f0 = ex2(m2[0] - mn0), f1 = ex2(m2[1] - mn1);
        m2[0] = mn0; m2[1] = mn1;

        float sum0 = 0.f, sum1 = 0.f;
#pragma unroll
        for (int nt = 0; nt < 8; nt++) {
            sc[nt][0] = ex2(sc[nt][0] - mn0);
            sc[nt][1] = ex2(sc[nt][1] - mn0);
            sc[nt][2] = ex2(sc[nt][2] - mn1);
            sc[nt][3] = ex2(sc[nt][3] - mn1);
            sum0 += sc[nt][0] + sc[nt][1];
            sum1 += sc[nt][2] + sc[nt][3];
        }
        sum0 += __shfl_xor_sync(0xffffffffu, sum0, 1);
        sum0 += __shfl_xor_sync(0xffffffffu, sum0, 2);
        sum1 += __shfl_xor_sync(0xffffffffu, sum1, 1);
        sum1 += __shfl_xor_sync(0xffffffffu, sum1, 2);
        l2[0] = l2[0] * f0 + sum0;
        l2[1] = l2[1] * f1 + sum1;

#pragma unroll
        for (int nt = 0; nt < 8; nt++) {
            o[nt][0] *= f0; o[nt][1] *= f0;
            o[nt][2] *= f1; o[nt][3] *= f1;
        }

        uint32_t pa[4][4];
#pragma unroll
        for (int j = 0; j < 4; j++) {
            pa[j][0] = h2pack(sc[2 * j + 0][0], sc[2 * j + 0][1]);
            pa[j][1] = h2pack(sc[2 * j + 0][2], sc[2 * j + 0][3]);
            pa[j][2] = h2pack(sc[2 * j + 1][0], sc[2 * j + 1][1]);
            pa[j][3] = h2pack(sc[2 * j + 1][2], sc[2 * j + 1][3]);
        }

#pragma unroll
        for (int j = 0; j < 4; j++) {
#pragma unroll
            for (int np = 0; np < 4; np++) {
                int kr = j * 16 + (lane & 7) + (((lane >> 3) & 1) << 3);
                int dc = np * 16 + ((lane >> 4) << 3);
                uint32_t v0, v1, v2, v3;
                ldsm4t(v0, v1, v2, v3,
                       smem_u32(&sV[kr * 128 + (((dc >> 3) ^ (kr & 7)) << 4)]));
                uint32_t bf0[2] = { v0, v1 }, bf1[2] = { v2, v3 };
                mma16816(o[2 * np + 0], pa[j], bf0);
                mma16816(o[2 * np + 1], pa[j], bf1);
            }
        }
        __syncthreads();
    }

    const float inv0 = 1.f / l2[0];
    const float inv1 = 1.f / l2[1];
    const int grow = b * SEQ + q0 + warp * 16 + g;
#pragma unroll
    for (int nt = 0; nt < 8; nt++) {
        int col = h * DHEAD + nt * 8 + 2 * tq;
        *reinterpret_cast<__half2*>(&ctxh[(size_t)grow * HDIM + col]) =
            __floats2half2_rn(o[nt][0] * inv0, o[nt][1] * inv0);
        *reinterpret_cast<__half2*>(&ctxh[(size_t)(grow + 8) * HDIM + col]) =
            __floats2half2_rn(o[nt][2] * inv1, o[nt][3] * inv1);
    }
}

// ---------------------------------------------------------------------------
extern "C" void kernel_launch(void* const* d_in, const int* in_sizes, int n_in,
                              void* d_out, int out_size)
{
    const float* query = (const float*)d_in[0];
    const float* key   = (const float*)d_in[1];
    const float* value = (const float*)d_in[2];
    const float* Wq    = (const float*)d_in[3];
    const float* bq    = (const float*)d_in[4];
    const float* Wk    = (const float*)d_in[5];
    const float* bk    = (const float*)d_in[6];
    const float* Wv    = (const float*)d_in[7];
    const float* bv    = (const float*)d_in[8];
    const float* Wo    = (const float*)d_in[9];
    const float* bo    = (const float*)d_in[10];
    float* out = (float*)d_out;

    __half *qh, *kh, *vh, *ctxh, *xq, *xk, *xv, *wqt, *wkt, *wvt, *wot;
    cudaGetSymbolAddress((void**)&qh,  g_qh);
    cudaGetSymbolAddress((void**)&kh,  g_kh);
    cudaGetSymbolAddress((void**)&vh,  g_vh);
    cudaGetSymbolAddress((void**)&ctxh, g_ctxh);
    cudaGetSymbolAddress((void**)&xq,  g_xq);
    cudaGetSymbolAddress((void**)&xk,  g_xk);
    cudaGetSymbolAddress((void**)&xv,  g_xv);
    cudaGetSymbolAddress((void**)&wqt, g_wqt);
    cudaGetSymbolAddress((void**)&wkt, g_wkt);
    cudaGetSymbolAddress((void**)&wvt, g_wvt);
    cudaGetSymbolAddress((void**)&wot, g_wot);

    // Prep: fp16 activations + transposed fp16 weights (converted once)
    cvt_inputs<<<dim3((MTOT * IDIM) / 1024, 1, 3), 256>>>(query, key, value, xq, xk, xv);
    transpose_w<<<dim3(HDIM / 32, IDIM / 32), 256>>>(Wq, wqt, IDIM, HDIM);
    transpose_w<<<dim3(DHEAD / 32, IDIM / 32), 256>>>(Wk, wkt, IDIM, DHEAD);
    transpose_w<<<dim3(DHEAD / 32, IDIM / 32), 256>>>(Wv, wvt, IDIM, DHEAD);
    transpose_w<<<dim3(IDIM / 32, HDIM / 32), 256>>>(Wo, wot, HDIM, IDIM);

    // Projections (fp16 both-side cp.async; Q pre-scaled into log2 domain)
    gemm_f16h<128, 128, true><<<dim3(HDIM / 128, MTOT / 128), 256>>>(
        xq, wqt, bq, qh, MTOT, HDIM, IDIM, QSCALE);
    gemm_f16h<64, 64, true><<<dim3(1, MTOT / 64), 256>>>(
        xk, wkt, bk, kh, MTOT, DHEAD, IDIM, 1.0f);
    gemm_f16h<64, 64, true><<<dim3(1, MTOT / 64), 256>>>(
        xv, wvt, bv, vh, MTOT, DHEAD, IDIM, 1.0f);

    // Attention (fragment fp16, round-8 validated)
    mqa_attn_f16<<<dim3(SEQ / 128, NHEADS, BATCH), 256>>>(qh, kh, vh, ctxh);

    // Output projection: fp16 A -> fp32 d_out
    gemm_f16h<128, 128, false><<<dim3(IDIM / 128, MTOT / 128), 256>>>(
        ctxh, wot, bo, out, MTOT, IDIM, HDIM, 1.0f);
}

// round 16
// speedup vs baseline: 7.1114x; 1.0027x over previous
#include <cuda_runtime.h>
#include <cuda_fp16.h>
#include <cstdint>

#define IDIM   1024
#define HDIM   1024
#define NHEADS 16
#define DHEAD  64
#define BATCH  2
#define SEQ    2048
#define MTOT   (BATCH * SEQ)   // 4096

// log2(e) / sqrt(HIDDEN_DIM) folded into the Q projection epilogue
#define QSCALE 0.04508422002570063f

// Scratch (allocation-free rule: __device__ globals), fp16 end-to-end
__device__ __half g_qh[(size_t)MTOT * HDIM];     // 8 MB
__device__ __half g_kh[(size_t)MTOT * DHEAD];
__device__ __half g_vh[(size_t)MTOT * DHEAD];
__device__ __half g_ctxh[(size_t)MTOT * HDIM];   // 8 MB
// fp16 activations (converted once)
__device__ __half g_xq[(size_t)MTOT * IDIM];     // 8 MB
__device__ __half g_xk[(size_t)MTOT * IDIM];     // 8 MB
__device__ __half g_xv[(size_t)MTOT * IDIM];     // 8 MB
// fp16 transposed weights [N, K]
__device__ __half g_wqt[(size_t)HDIM * IDIM];    // 2 MB
__device__ __half g_wkt[(size_t)DHEAD * IDIM];
__device__ __half g_wvt[(size_t)DHEAD * IDIM];
__device__ __half g_wot[(size_t)IDIM * HDIM];    // 2 MB

__device__ __forceinline__ uint32_t smem_u32(const void* p) {
    return static_cast<uint32_t>(__cvta_generic_to_shared(p));
}
__device__ __forceinline__ uint32_t h2pack(float a, float b) {
    __half2 h = __floats2half2_rn(a, b);
    return *reinterpret_cast<uint32_t*>(&h);
}
__device__ __forceinline__ float ex2(float x) {
    float y;
    asm("ex2.approx.ftz.f32 %0, %1;" : "=f"(y) : "f"(x));
    return y;
}
// packed half2 2^x
__device__ __forceinline__ uint32_t ex2h2(uint32_t x) {
    uint32_t y;
    asm("ex2.approx.f16x2 %0, %1;" : "=r"(y) : "r"(x));
    return y;
}
__device__ __forceinline__ void cp16(uint32_t dst, const void* src) {
    asm volatile("cp.async.cg.shared.global [%0], [%1], 16;" :: "r"(dst), "l"(src));
}
#define CP_COMMIT() asm volatile("cp.async.commit_group;")
template <int N>
__device__ __forceinline__ void cp_wait() {
    asm volatile("cp.async.wait_group %0;" :: "n"(N));
}

// D += A(16x16) * B(16x8), fp16 in / fp32 accum.
__device__ __forceinline__ void mma16816(float (&d)[4], const uint32_t (&a)[4],
                                         const uint32_t (&b)[2]) {
    asm volatile(
        "mma.sync.aligned.m16n8k16.row.col.f32.f16.f16.f32 "
        "{%0,%1,%2,%3}, {%4,%5,%6,%7}, {%8,%9}, {%0,%1,%2,%3};"
        : "+f"(d[0]), "+f"(d[1]), "+f"(d[2]), "+f"(d[3])
        : "r"(a[0]), "r"(a[1]), "r"(a[2]), "r"(a[3]), "r"(b[0]), "r"(b[1]));
}
__device__ __forceinline__ void ldsm4(uint32_t& r0, uint32_t& r1, uint32_t& r2,
                                      uint32_t& r3, uint32_t a) {
    asm volatile("ldmatrix.sync.aligned.m8n8.x4.shared.b16 {%0,%1,%2,%3}, [%4];"
                 : "=r"(r0), "=r"(r1), "=r"(r2), "=r"(r3) : "r"(a));
}
__device__ __forceinline__ void ldsm4t(uint32_t& r0, uint32_t& r1, uint32_t& r2,
                                       uint32_t& r3, uint32_t a) {
    asm volatile("ldmatrix.sync.aligned.m8n8.x4.trans.shared.b16 {%0,%1,%2,%3}, [%4];"
                 : "=r"(r0), "=r"(r1), "=r"(r2), "=r"(r3) : "r"(a));
}

// ---------------------------------------------------------------------------
// Prep: fp32 -> fp16 activation convert (once per tensor)
// ---------------------------------------------------------------------------
__global__ void __launch_bounds__(256)
cvt_inputs(const float* __restrict__ q, const float* __restrict__ k,
           const float* __restrict__ v, __half* __restrict__ oq,
           __half* __restrict__ ok, __half* __restrict__ ov)
{
    const float* src = blockIdx.z == 0 ? q : (blockIdx.z == 1 ? k : v);
    __half* dst = blockIdx.z == 0 ? oq : (blockIdx.z == 1 ? ok : ov);
    size_t i = ((size_t)blockIdx.x * 256 + threadIdx.x) * 4;
    float4 x = *reinterpret_cast<const float4*>(src + i);
    uint2 hh = { h2pack(x.x, x.y), h2pack(x.z, x.w) };
    *reinterpret_cast<uint2*>(dst + i) = hh;
}

// Prep: W [K,N] fp32 -> Wt [N,K] fp16 (tiled transpose)
__global__ void __launch_bounds__(256)
transpose_w(const float* __restrict__ in, __half* __restrict__ out, int K, int N)
{
    __shared__ float t[32][33];
    int k0 = blockIdx.y * 32, n0 = blockIdx.x * 32;
    int tx = threadIdx.x & 31, ty = threadIdx.x >> 5;   // 32 x 8
#pragma unroll
    for (int i = 0; i < 4; i++)
        t[ty + 8 * i][tx] = in[(size_t)(k0 + ty + 8 * i) * N + n0 + tx];
    __syncthreads();
#pragma unroll
    for (int i = 0; i < 4; i++)
        out[(size_t)(n0 + ty + 8 * i) * K + k0 + tx] = __float2half(t[tx][ty + 8 * i]);
}

// ---------------------------------------------------------------------------
// fp16 fragment GEMM, both operands cp.async (round-15 validated, unchanged):
// C[M,N] = A[M,K] @ Bt[N,K]^T + bias.
// ---------------------------------------------------------------------------
template <int BM, int BN, bool OHALF>
__global__ void __launch_bounds__(256)
gemm_f16h(const __half* __restrict__ A, const __half* __restrict__ Bt,
          const float* __restrict__ bias, void* __restrict__ Cp,
          int M, int N, int K, float oscale)
{
    constexpr int MT  = (BM / 2) / 16;
    constexpr int NT  = (BN / 4) / 8;
    constexpr int ACH = BM * 4 / 256;
    constexpr int WCH = BN * 4 / 256;

    __shared__ __align__(16) uint8_t sA[2][BM * 64];
    __shared__ __align__(16) uint8_t sW[2][BN * 64];

    const int tid  = threadIdx.x;
    const int lane = tid & 31;
    const int warp = tid >> 5;
    const int wm   = warp >> 2;
    const int wn   = warp & 3;
    const int m0   = blockIdx.y * BM;
    const int n0   = blockIdx.x * BN;

    float acc[MT][NT][4];
#pragma unroll
    for (int i = 0; i < MT; i++)
#pragma unroll
        for (int j = 0; j < NT; j++)
#pragma unroll
            for (int e = 0; e < 4; e++) acc[i][j][e] = 0.f;

    auto fill = [&](int s, int kk) {
#pragma unroll
        for (int i = 0; i < ACH; i++) {
            int idx = tid + i * 256;
            int r = idx >> 2, c = idx & 3;
            cp16(smem_u32(&sA[s][r * 64 + ((c ^ ((r >> 1) & 3)) << 4)]),
                 A + (size_t)(m0 + r) * K + kk + c * 8);
        }
#pragma unroll
        for (int i = 0; i < WCH; i++) {
            int idx = tid + i * 256;
            int r = idx >> 2, c = idx & 3;
            cp16(smem_u32(&sW[s][r * 64 + ((c ^ ((r >> 1) & 3)) << 4)]),
                 Bt + (size_t)(n0 + r) * K + kk + c * 8);
        }
        CP_COMMIT();
    };

    fill(0, 0);

    const int NITER = K / 32;
    for (int t = 0; t < NITER; t++) {
        const int s = t & 1;
        if (t + 1 < NITER) {
            fill(s ^ 1, (t + 1) * 32);
            cp_wait<1>();
        } else {
            cp_wait<0>();
        }
        __syncthreads();

#pragma unroll
        for (int ks = 0; ks < 2; ks++) {
            const int c0 = ks * 16;
            uint32_t af[MT][4];
#pragma unroll
            for (int mi = 0; mi < MT; mi++) {
                int row = wm * (BM / 2) + mi * 16 + (lane & 15);
                int hc = c0 + ((lane >> 4) << 3);
                ldsm4(af[mi][0], af[mi][1], af[mi][2], af[mi][3],
                      smem_u32(&sA[s][row * 64 + (((hc >> 3) ^ ((row >> 1) & 3)) << 4)]));
            }
#pragma unroll
            for (int np = 0; np < NT / 2; np++) {
                int nr = wn * (BN / 4) + np * 16 + (lane & 7) + ((lane >> 4) << 3);
                int hc = c0 + (((lane >> 3) & 1) << 3);
                uint32_t b0, b1, b2, b3;
                ldsm4(b0, b1, b2, b3,
                      smem_u32(&sW[s][nr * 64 + (((hc >> 3) ^ ((nr >> 1) & 3)) << 4)]));
                uint32_t bf0[2] = { b0, b1 }, bf1[2] = { b2, b3 };
#pragma unroll
                for (int mi = 0; mi < MT; mi++) {
                    mma16816(acc[mi][2 * np + 0], af[mi], bf0);
                    mma16816(acc[mi][2 * np + 1], af[mi], bf1);
                }
            }
        }
        __syncthreads();
    }

    float*  Cf = (float*)Cp;
    __half* Ch = (__half*)Cp;
#pragma unroll
    for (int mi = 0; mi < MT; mi++) {
        int row = m0 + wm * (BM / 2) + mi * 16 + (lane >> 2);
#pragma unroll
        for (int ni = 0; ni < NT; ni++) {
            int col = n0 + wn * (BN / 4) + ni * 8 + 2 * (lane & 3);
            float b0 = bias[col], b1 = bias[col + 1];
            float v00 = (acc[mi][ni][0] + b0) * oscale;
            float v01 = (acc[mi][ni][1] + b1) * oscale;
            float v10 = (acc[mi][ni][2] + b0) * oscale;
            float v11 = (acc[mi][ni][3] + b1) * oscale;
            if (OHALF) {
                *reinterpret_cast<__half2*>(&Ch[(size_t)row * N + col]) =
                    __floats2half2_rn(v00, v01);
                *reinterpret_cast<__half2*>(&Ch[(size_t)(row + 8) * N + col]) =
                    __floats2half2_rn(v10, v11);
            } else {
                *reinterpret_cast<float2*>(&Cf[(size_t)row * N + col]) =
                    make_float2(v00, v01);
                *reinterpret_cast<float2*>(&Cf[(size_t)(row + 8) * N + col]) =
                    make_float2(v10, v11);
            }
        }
    }
}

// ---------------------------------------------------------------------------
// fp16 MQA flash attention. Round-16 softmax: P exponentials via
// ex2.approx.f16x2 (packed), row-sum l accumulated by an extra MMA against a
// constant all-ones B fragment (no smem, rescales like O). No per-tile
// sum/shfl; numerator and denominator use the identical fp16 P.
// ---------------------------------------------------------------------------
__global__ void __launch_bounds__(256)
mqa_attn_f16(const __half* __restrict__ Qh, const __half* __restrict__ Kh,
             const __half* __restrict__ Vh, __half* __restrict__ ctxh)
{
    __shared__ __align__(16) uint8_t smem[32768];
    const int OFF_K[2] = { 16384, 0 };
    const int OFF_V[2] = { 24576, 8192 };

    const int tid  = threadIdx.x;
    const int lane = tid & 31;
    const int warp = tid >> 5;
    const int b    = blockIdx.z;
    const int h    = blockIdx.y;
    const int q0   = blockIdx.x * 128;
    const int g    = lane >> 2;
    const int tq   = lane & 3;

    const __half* kg = Kh + (size_t)b * SEQ * DHEAD;
    const __half* vg = Vh + (size_t)b * SEQ * DHEAD;

    {
        const __half* qb = Qh + (size_t)(b * SEQ + q0) * HDIM + h * DHEAD;
#pragma unroll
        for (int i = 0; i < 4; i++) {
            int idx = tid + i * 256;
            int r = idx >> 3, c = idx & 7;
            cp16(smem_u32(&smem[r * 128 + ((c ^ (r & 7)) << 4)]),
                 qb + (size_t)r * HDIM + c * 8);
        }
#pragma unroll
        for (int i = 0; i < 2; i++) {
            int idx = tid + i * 256;
            int r = idx >> 3, c = idx & 7;
            int off = r * 128 + ((c ^ (r & 7)) << 4);
            cp16(smem_u32(&smem[OFF_K[0] + off]), kg + (size_t)r * DHEAD + c * 8);
            cp16(smem_u32(&smem[OFF_V[0] + off]), vg + (size_t)r * DHEAD + c * 8);
        }
        CP_COMMIT();
    }
    cp_wait<0>();
    __syncthreads();

    uint32_t qa[4][4];
#pragma unroll
    for (int ks = 0; ks < 4; ks++) {
        int row = warp * 16 + (lane & 15);
        int hc = ks * 16 + ((lane >> 4) << 3);
        ldsm4(qa[ks][0], qa[ks][1], qa[ks][2], qa[ks][3],
              smem_u32(&smem[row * 128 + (((hc >> 3) ^ (row & 7)) << 4)]));
    }
    __syncthreads();

    float m2[2] = { -1e30f, -1e30f };
    float o[8][4];
    float lacc[4] = { 0.f, 0.f, 0.f, 0.f };   // l in a C-fragment (cols identical)
#pragma unroll
    for (int i = 0; i < 8; i++)
#pragma unroll
        for (int j = 0; j < 4; j++) o[i][j] = 0.f;

    const uint32_t ones2 = 0x3C003C00u;        // half2(1.0, 1.0)
    const uint32_t bones[2] = { ones2, ones2 };

    const int NT_KV = SEQ / 64;
    for (int t = 0; t < NT_KV; t++) {
        const int s = t & 1;

        if (t + 1 < NT_KV) {
            const int kt = (t + 1) * 64;
#pragma unroll
            for (int i = 0; i < 2; i++) {
                int idx = tid + i * 256;
                int r = idx >> 3, c = idx & 7;
                int off = r * 128 + ((c ^ (r & 7)) << 4);
                cp16(smem_u32(&smem[OFF_K[s ^ 1] + off]),
                     kg + (size_t)(kt + r) * DHEAD + c * 8);
                cp16(smem_u32(&smem[OFF_V[s ^ 1] + off]),
                     vg + (size_t)(kt + r) * DHEAD + c * 8);
            }
            CP_COMMIT();
            cp_wait<1>();
        } else {
            cp_wait<0>();
        }
        __syncthreads();

        const uint8_t* sK = &smem[OFF_K[s]];
        const uint8_t* sV = &smem[OFF_V[s]];

        // S = Q @ K^T : m16 x n64 x k64 (log2 domain)
        float sc[8][4];
#pragma unroll
        for (int nt = 0; nt < 8; nt++)
#pragma unroll
            for (int e = 0; e < 4; e++) sc[nt][e] = 0.f;

#pragma unroll
        for (int ks = 0; ks < 4; ks++) {
#pragma unroll
            for (int np = 0; np < 4; np++) {
                int nr = np * 16 + (lane & 7) + ((lane >> 4) << 3);
                int hc = ks * 16 + (((lane >> 3) & 1) << 3);
                uint32_t k0, k1, k2, k3;
                ldsm4(k0, k1, k2, k3,
                      smem_u32(&sK[nr * 128 + (((hc >> 3) ^ (nr & 7)) << 4)]));
                uint32_t bf0[2] = { k0, k1 }, bf1[2] = { k2, k3 };
                mma16816(sc[2 * np + 0], qa[ks], bf0);
                mma16816(sc[2 * np + 1], qa[ks], bf1);
            }
        }

        // online softmax max update (rows g / g+8)
        float mx0 = -1e30f, mx1 = -1e30f;
#pragma unroll
        for (int nt = 0; nt < 8; nt++) {
            mx0 = fmaxf(mx0, fmaxf(sc[nt][0], sc[nt][1]));
            mx1 = fmaxf(mx1, fmaxf(sc[nt][2], sc[nt][3]));
        }
        mx0 = fmaxf(mx0, __shfl_xor_sync(0xffffffffu, mx0, 1));
        mx0 = fmaxf(mx0, __shfl_xor_sync(0xffffffffu, mx0, 2));
        mx1 = fmaxf(mx1, __shfl_xor_sync(0xffffffffu, mx1, 1));
        mx1 = fmaxf(mx1, __shfl_xor_sync(0xffffffffu, mx1, 2));

        float mn0 = fmaxf(m2[0], mx0), mn1 = fmaxf(m2[1], mx1);
        float f0 = ex2(m2[0] - mn0), f1 = ex2(m2[1] - mn1);
        m2[0] = mn0; m2[1] = mn1;

        // rescale O and l accumulators
#pragma unroll
        for (int nt = 0; nt < 8; nt++) {
            o[nt][0] *= f0; o[nt][1] *= f0;
            o[nt][2] *= f1; o[nt][3] *= f1;
        }
        lacc[0] *= f0; lacc[1] *= f0;
        lacc[2] *= f1; lacc[3] *= f1;

        // P = 2^(S - m), packed fp16 A-fragments directly
        uint32_t pa[4][4];
#pragma unroll
        for (int j = 0; j < 4; j++) {
            pa[j][0] = ex2h2(h2pack(sc[2 * j + 0][0] - mn0, sc[2 * j + 0][1] - mn0));
            pa[j][1] = ex2h2(h2pack(sc[2 * j + 0][2] - mn1, sc[2 * j + 0][3] - mn1));
            pa[j][2] = ex2h2(h2pack(sc[2 * j + 1][0] - mn0, sc[2 * j + 1][1] - mn0));
            pa[j][3] = ex2h2(h2pack(sc[2 * j + 1][2] - mn1, sc[2 * j + 1][3] - mn1));
        }

        // l += P @ ones  (one n=8 MMA per 16-key step, constant B)
#pragma unroll
        for (int j = 0; j < 4; j++)
            mma16816(lacc, pa[j], bones);

        // O += P @ V, V via ldmatrix.trans
#pragma unroll
        for (int j = 0; j < 4; j++) {
#pragma unroll
            for (int np = 0; np < 4; np++) {
                int kr = j * 16 + (lane & 7) + (((lane >> 3) & 1) << 3);
                int dc = np * 16 + ((lane >> 4) << 3);
                uint32_t v0, v1, v2, v3;
                ldsm4t(v0, v1, v2, v3,
                       smem_u32(&sV[kr * 128 + (((dc >> 3) ^ (kr & 7)) << 4)]));
                uint32_t bf0[2] = { v0, v1 }, bf1[2] = { v2, v3 };
                mma16816(o[2 * np + 0], pa[j], bf0);
                mma16816(o[2 * np + 1], pa[j], bf1);
            }
        }
        __syncthreads();
    }

    // finalize: l sits in lacc (cols identical: c0 = row g, c2 = row g+8)
    const float inv0 = 1.f / lacc[0];
    const float inv1 = 1.f / lacc[2];
    const int grow = b * SEQ + q0 + warp * 16 + g;
#pragma unroll
    for (int nt = 0; nt < 8; nt++) {
        int col = h * DHEAD + nt * 8 + 2 * tq;
        *reinterpret_cast<__half2*>(&ctxh[(size_t)grow * HDIM + col]) =
            __floats2half2_rn(o[nt][0] * inv0, o[nt][1] * inv0);
        *reinterpret_cast<__half2*>(&ctxh[(size_t)(grow + 8) * HDIM + col]) =
            __floats2half2_rn(o[nt][2] * inv1, o[nt][3] * inv1);
    }
}

// ---------------------------------------------------------------------------
extern "C" void kernel_launch(void* const* d_in, const int* in_sizes, int n_in,
                              void* d_out, int out_size)
{
    const float* query = (const float*)d_in[0];
    const float* key   = (const float*)d_in[1];
    const float* value = (const float*)d_in[2];
    const float* Wq    = (const float*)d_in[3];
    const float* bq    = (const float*)d_in[4];
    const float* Wk    = (const float*)d_in[5];
    const float* bk    = (const float*)d_in[6];
    const float* Wv    = (const float*)d_in[7];
    const float* bv    = (const float*)d_in[8];
    const float* Wo    = (const float*)d_in[9];
    const float* bo    = (const float*)d_in[10];
    float* out = (float*)d_out;

    __half *qh, *kh, *vh, *ctxh, *xq, *xk, *xv, *wqt, *wkt, *wvt, *wot;
    cudaGetSymbolAddress((void**)&qh,  g_qh);
    cudaGetSymbolAddress((void**)&kh,  g_kh);
    cudaGetSymbolAddress((void**)&vh,  g_vh);
    cudaGetSymbolAddress((void**)&ctxh, g_ctxh);
    cudaGetSymbolAddress((void**)&xq,  g_xq);
    cudaGetSymbolAddress((void**)&xk,  g_xk);
    cudaGetSymbolAddress((void**)&xv,  g_xv);
    cudaGetSymbolAddress((void**)&wqt, g_wqt);
    cudaGetSymbolAddress((void**)&wkt, g_wkt);
    cudaGetSymbolAddress((void**)&wvt, g_wvt);
    cudaGetSymbolAddress((void**)&wot, g_wot);

    // Prep: fp16 activations + transposed fp16 weights (converted once)
    cvt_inputs<<<dim3((MTOT * IDIM) / 1024, 1, 3), 256>>>(query, key, value, xq, xk, xv);
    transpose_w<<<dim3(HDIM / 32, IDIM / 32), 256>>>(Wq, wqt, IDIM, HDIM);
    transpose_w<<<dim3(DHEAD / 32, IDIM / 32), 256>>>(Wk, wkt, IDIM, DHEAD);
    transpose_w<<<dim3(DHEAD / 32, IDIM / 32), 256>>>(Wv, wvt, IDIM, DHEAD);
    transpose_w<<<dim3(IDIM / 32, HDIM / 32), 256>>>(Wo, wot, HDIM, IDIM);

    // Projections (fp16 both-side cp.async; Q pre-scaled into log2 domain)
    gemm_f16h<128, 128, true><<<dim3(HDIM / 128, MTOT / 128), 256>>>(
        xq, wqt, bq, qh, MTOT, HDIM, IDIM, QSCALE);
    gemm_f16h<64, 64, true><<<dim3(1, MTOT / 64), 256>>>(
        xk, wkt, bk, kh, MTOT, DHEAD, IDIM, 1.0f);
    gemm_f16h<64, 64, true><<<dim3(1, MTOT / 64), 256>>>(
        xv, wvt, bv, vh, MTOT, DHEAD, IDIM, 1.0f);

    // Attention (fragment fp16, ones-MMA l, f16x2 ex2)
    mqa_attn_f16<<<dim3(SEQ / 128, NHEADS, BATCH), 256>>>(qh, kh, vh, ctxh);

    // Output projection: fp16 A -> fp32 d_out
    gemm_f16h<128, 128, false><<<dim3(IDIM / 128, MTOT / 128), 256>>>(
        ctxh, wot, bo, out, MTOT, IDIM, HDIM, 1.0f);
}